// round 1
// baseline (speedup 1.0000x reference)
#include <cuda_runtime.h>
#include <math.h>

// Problem constants
#define BB    2
#define SS    2048
#define HH    2560
#define NHQ   8
#define NKV   4
#define DD    256
#define SWIN  1024
#define MROWS (BB*SS)          // 4096
#define QCOLS (NHQ*DD)         // 2048
#define KVCOLS (NKV*DD)        // 1024

// Scratch (allocation-free rule: device globals)
__device__ float g_q [ (size_t)MROWS * QCOLS ];   // 32MB
__device__ float g_k [ (size_t)MROWS * KVCOLS ];  // 16MB
__device__ float g_v [ (size_t)MROWS * KVCOLS ];  // 16MB
__device__ float g_ao[ (size_t)MROWS * QCOLS ];   // 32MB

// ---------------------------------------------------------------------------
// SGEMM C[M,N] = A[M,K] (row-major) * B[N,K]^T (row-major)  — "NT" layout.
// 128x128 tile, BK=8, 256 threads, 8x8 micro-tile, global prefetch.
// M,N multiples of 128; K multiple of 8. All satisfied here.
// ---------------------------------------------------------------------------
__global__ void __launch_bounds__(256) sgemm_nt(
    const float* __restrict__ A, const float* __restrict__ B,
    float* __restrict__ C, int M, int N, int K)
{
    __shared__ float As[8][128];
    __shared__ float Bs[8][128];

    const int t  = threadIdx.x;
    const int m0 = blockIdx.y * 128;
    const int n0 = blockIdx.x * 128;
    const int lr = t >> 1;           // 0..127 (row within tile)
    const int lc = (t & 1) << 2;     // 0 or 4 (k-subchunk)
    const int ty = t >> 4;           // 0..15
    const int tx = t & 15;           // 0..15

    const float* Ap = A + (size_t)(m0 + lr) * K + lc;
    const float* Bp = B + (size_t)(n0 + lr) * K + lc;

    float acc[8][8];
#pragma unroll
    for (int i = 0; i < 8; i++)
#pragma unroll
        for (int j = 0; j < 8; j++) acc[i][j] = 0.f;

    float4 av = *(const float4*)Ap;
    float4 bv = *(const float4*)Bp;

    for (int k0 = 0; k0 < K; k0 += 8) {
        As[lc+0][lr] = av.x; As[lc+1][lr] = av.y;
        As[lc+2][lr] = av.z; As[lc+3][lr] = av.w;
        Bs[lc+0][lr] = bv.x; Bs[lc+1][lr] = bv.y;
        Bs[lc+2][lr] = bv.z; Bs[lc+3][lr] = bv.w;
        __syncthreads();

        if (k0 + 8 < K) {
            av = *(const float4*)(Ap + k0 + 8);
            bv = *(const float4*)(Bp + k0 + 8);
        }

#pragma unroll
        for (int kk = 0; kk < 8; kk++) {
            float a[8], b[8];
            *(float4*)&a[0] = *(const float4*)&As[kk][ty*8];
            *(float4*)&a[4] = *(const float4*)&As[kk][ty*8+4];
            *(float4*)&b[0] = *(const float4*)&Bs[kk][tx*8];
            *(float4*)&b[4] = *(const float4*)&Bs[kk][tx*8+4];
#pragma unroll
            for (int i = 0; i < 8; i++)
#pragma unroll
                for (int j = 0; j < 8; j++)
                    acc[i][j] += a[i] * b[j];
        }
        __syncthreads();
    }

#pragma unroll
    for (int i = 0; i < 8; i++) {
        float* Cp = C + (size_t)(m0 + ty*8 + i) * N + n0 + tx*8;
        *(float4*)(Cp + 0) = make_float4(acc[i][0], acc[i][1], acc[i][2], acc[i][3]);
        *(float4*)(Cp + 4) = make_float4(acc[i][4], acc[i][5], acc[i][6], acc[i][7]);
    }
}

// ---------------------------------------------------------------------------
// RMSNorm (+ optional weight) + RoPE, in-place on g_q/g_k/g_v.
// grid = (4096 rows, 16 parts): parts 0-7 = q heads, 8-11 = k heads, 12-15 = v.
// 256 threads = one d each.
// ---------------------------------------------------------------------------
__global__ void rmsrope_kernel(const float* __restrict__ cosb,
                               const float* __restrict__ sinb,
                               const float* __restrict__ qw,
                               const float* __restrict__ kw)
{
    const int row  = blockIdx.x;      // b*S + s
    const int part = blockIdx.y;      // 0..15
    const int d    = threadIdx.x;     // 0..255

    float* ptr;
    const float* w = nullptr;
    bool do_rope = true;
    if (part < 8) {
        ptr = g_q + (size_t)row * QCOLS + part * DD; w = qw;
    } else if (part < 12) {
        ptr = g_k + (size_t)row * KVCOLS + (part - 8) * DD; w = kw;
    } else {
        ptr = g_v + (size_t)row * KVCOLS + (part - 12) * DD; do_rope = false;
    }

    float x = ptr[d];

    // block reduce sum of squares over 256 threads
    __shared__ float red[8];
    float ss = x * x;
#pragma unroll
    for (int o = 16; o; o >>= 1) ss += __shfl_xor_sync(0xffffffffu, ss, o);
    if ((d & 31) == 0) red[d >> 5] = ss;
    __syncthreads();
    float tot = red[0]+red[1]+red[2]+red[3]+red[4]+red[5]+red[6]+red[7];

    float y = x * rsqrtf(tot * (1.0f / DD) + 1e-6f);
    if (w) y *= (1.0f + w[d]);

    if (do_rope) {
        __shared__ float yb[DD];
        yb[d] = y;
        __syncthreads();
        int s = row & (SS - 1);
        float c  = cosb[(size_t)s * DD + d];
        float sn = sinb[(size_t)s * DD + d];
        float other = yb[d ^ 128];
        y = (d < 128) ? (y * c - other * sn) : (y * c + other * sn);
    }
    ptr[d] = y;
}

// ---------------------------------------------------------------------------
// Sliding-window causal flash attention, fp32 SIMT.
// grid = (S/64, NH, B), 256 threads. BQ=BK=64, D=256, scale=1.0.
// Thread (ty=t>>4, tx=t&15): S micro-tile 4q x 4k ; O micro-tile 4q x 16d.
// ---------------------------------------------------------------------------
__global__ void __launch_bounds__(256) attn_kernel()
{
    const int qblk = blockIdx.x;
    const int h    = blockIdx.y;
    const int b    = blockIdx.z;
    const int kvh  = h >> 1;            // repeat_interleave, g=2
    const int t  = threadIdx.x;
    const int ty = t >> 4, tx = t & 15;
    const int ty4 = ty * 4, tx4 = tx * 4;
    const int qs = qblk * 64;

    __shared__ float Qc[8][65];
    __shared__ float Kc[8][65];
    __shared__ float Ss[64][65];
    __shared__ float Vc[8][256];

    float o[4][16];
#pragma unroll
    for (int i = 0; i < 4; i++)
#pragma unroll
        for (int j = 0; j < 16; j++) o[i][j] = 0.f;
    float m[4] = {-1e30f, -1e30f, -1e30f, -1e30f};
    float l[4] = {0.f, 0.f, 0.f, 0.f};

    const float* qbase = g_q + ((size_t)(b * SS + qs)) * QCOLS + h * DD;
    const float* kbase = g_k + ((size_t)(b * SS)) * KVCOLS + kvh * DD;
    const float* vbase = g_v + ((size_t)(b * SS)) * KVCOLS + kvh * DD;

    int ks_min = qs - (SWIN - 1);
    if (ks_min < 0) ks_min = 0;
    const int t0 = ks_min >> 6;

    for (int kt = t0; kt <= qblk; kt++) {
        const int ks = kt << 6;

        // ---- S = Q K^T (stream d in chunks of 8) ----
        float sacc[4][4];
#pragma unroll
        for (int i = 0; i < 4; i++)
#pragma unroll
            for (int j = 0; j < 4; j++) sacc[i][j] = 0.f;

        for (int d0 = 0; d0 < DD; d0 += 8) {
            __syncthreads();
            {
                int tt = t & 127;
                int r  = tt >> 1;
                int dd = (tt & 1) << 2;
                if (t < 128) {
                    float4 v = *(const float4*)(qbase + (size_t)r * QCOLS + d0 + dd);
                    Qc[dd+0][r] = v.x; Qc[dd+1][r] = v.y;
                    Qc[dd+2][r] = v.z; Qc[dd+3][r] = v.w;
                } else {
                    float4 v = *(const float4*)(kbase + (size_t)(ks + r) * KVCOLS + d0 + dd);
                    Kc[dd+0][r] = v.x; Kc[dd+1][r] = v.y;
                    Kc[dd+2][r] = v.z; Kc[dd+3][r] = v.w;
                }
            }
            __syncthreads();
#pragma unroll
            for (int dd = 0; dd < 8; dd++) {
                float a0 = Qc[dd][ty4+0], a1 = Qc[dd][ty4+1];
                float a2 = Qc[dd][ty4+2], a3 = Qc[dd][ty4+3];
                float b0 = Kc[dd][tx4+0], b1 = Kc[dd][tx4+1];
                float b2 = Kc[dd][tx4+2], b3 = Kc[dd][tx4+3];
                sacc[0][0] += a0*b0; sacc[0][1] += a0*b1; sacc[0][2] += a0*b2; sacc[0][3] += a0*b3;
                sacc[1][0] += a1*b0; sacc[1][1] += a1*b1; sacc[1][2] += a1*b2; sacc[1][3] += a1*b3;
                sacc[2][0] += a2*b0; sacc[2][1] += a2*b1; sacc[2][2] += a2*b2; sacc[2][3] += a2*b3;
                sacc[3][0] += a3*b0; sacc[3][1] += a3*b1; sacc[3][2] += a3*b2; sacc[3][3] += a3*b3;
            }
        }

        // ---- mask + online softmax update ----
#pragma unroll
        for (int i = 0; i < 4; i++) {
            const int qi = qs + ty4 + i;
#pragma unroll
            for (int j = 0; j < 4; j++) {
                const int kj = ks + tx4 + j;
                if (kj > qi || kj <= qi - SWIN) sacc[i][j] = -1e30f;
            }
            float mi = fmaxf(fmaxf(sacc[i][0], sacc[i][1]), fmaxf(sacc[i][2], sacc[i][3]));
#pragma unroll
            for (int off = 8; off; off >>= 1)
                mi = fmaxf(mi, __shfl_xor_sync(0xffffffffu, mi, off));
            const float mnew = fmaxf(m[i], mi);
            const float corr = __expf(m[i] - mnew);
            float rsum = 0.f;
#pragma unroll
            for (int j = 0; j < 4; j++) {
                float p = (sacc[i][j] <= -1e29f) ? 0.f : __expf(sacc[i][j] - mnew);
                Ss[ty4 + i][tx4 + j] = p;
                rsum += p;
            }
#pragma unroll
            for (int off = 8; off; off >>= 1)
                rsum += __shfl_xor_sync(0xffffffffu, rsum, off);
            l[i] = l[i] * corr + rsum;
            m[i] = mnew;
#pragma unroll
            for (int j = 0; j < 16; j++) o[i][j] *= corr;
        }

        // ---- O += P V (stream keys in chunks of 8) ----
        for (int k0 = 0; k0 < 64; k0 += 8) {
            __syncthreads();   // also orders Ss writes above vs reads below
#pragma unroll
            for (int u = 0; u < 2; u++) {
                int e  = t + u * 256;          // 0..511
                int r  = e >> 6;               // 0..7
                int dd = (e & 63) << 2;
                float4 v = *(const float4*)(vbase + (size_t)(ks + k0 + r) * KVCOLS + dd);
                *(float4*)&Vc[r][dd] = v;
            }
            __syncthreads();
#pragma unroll
            for (int kk = 0; kk < 8; kk++) {
                float p0 = Ss[ty4+0][k0+kk];
                float p1 = Ss[ty4+1][k0+kk];
                float p2 = Ss[ty4+2][k0+kk];
                float p3 = Ss[ty4+3][k0+kk];
                float4 v0 = *(const float4*)&Vc[kk][tx*16 + 0];
                float4 v1 = *(const float4*)&Vc[kk][tx*16 + 4];
                float4 v2 = *(const float4*)&Vc[kk][tx*16 + 8];
                float4 v3 = *(const float4*)&Vc[kk][tx*16 + 12];
                o[0][0]+=p0*v0.x; o[0][1]+=p0*v0.y; o[0][2]+=p0*v0.z; o[0][3]+=p0*v0.w;
                o[0][4]+=p0*v1.x; o[0][5]+=p0*v1.y; o[0][6]+=p0*v1.z; o[0][7]+=p0*v1.w;
                o[0][8]+=p0*v2.x; o[0][9]+=p0*v2.y; o[0][10]+=p0*v2.z; o[0][11]+=p0*v2.w;
                o[0][12]+=p0*v3.x; o[0][13]+=p0*v3.y; o[0][14]+=p0*v3.z; o[0][15]+=p0*v3.w;
                o[1][0]+=p1*v0.x; o[1][1]+=p1*v0.y; o[1][2]+=p1*v0.z; o[1][3]+=p1*v0.w;
                o[1][4]+=p1*v1.x; o[1][5]+=p1*v1.y; o[1][6]+=p1*v1.z; o[1][7]+=p1*v1.w;
                o[1][8]+=p1*v2.x; o[1][9]+=p1*v2.y; o[1][10]+=p1*v2.z; o[1][11]+=p1*v2.w;
                o[1][12]+=p1*v3.x; o[1][13]+=p1*v3.y; o[1][14]+=p1*v3.z; o[1][15]+=p1*v3.w;
                o[2][0]+=p2*v0.x; o[2][1]+=p2*v0.y; o[2][2]+=p2*v0.z; o[2][3]+=p2*v0.w;
                o[2][4]+=p2*v1.x; o[2][5]+=p2*v1.y; o[2][6]+=p2*v1.z; o[2][7]+=p2*v1.w;
                o[2][8]+=p2*v2.x; o[2][9]+=p2*v2.y; o[2][10]+=p2*v2.z; o[2][11]+=p2*v2.w;
                o[2][12]+=p2*v3.x; o[2][13]+=p2*v3.y; o[2][14]+=p2*v3.z; o[2][15]+=p2*v3.w;
                o[3][0]+=p3*v0.x; o[3][1]+=p3*v0.y; o[3][2]+=p3*v0.z; o[3][3]+=p3*v0.w;
                o[3][4]+=p3*v1.x; o[3][5]+=p3*v1.y; o[3][6]+=p3*v1.z; o[3][7]+=p3*v1.w;
                o[3][8]+=p3*v2.x; o[3][9]+=p3*v2.y; o[3][10]+=p3*v2.z; o[3][11]+=p3*v2.w;
                o[3][12]+=p3*v3.x; o[3][13]+=p3*v3.y; o[3][14]+=p3*v3.z; o[3][15]+=p3*v3.w;
            }
        }
    }

    // ---- epilogue: divide by l, write ----
    float* obase = g_ao + ((size_t)(b * SS + qs)) * QCOLS + h * DD;
#pragma unroll
    for (int i = 0; i < 4; i++) {
        const float inv = 1.0f / l[i];
        float* op = obase + (size_t)(ty4 + i) * QCOLS + tx * 16;
#pragma unroll
        for (int j4 = 0; j4 < 4; j4++) {
            float4 w;
            w.x = o[i][j4*4+0] * inv; w.y = o[i][j4*4+1] * inv;
            w.z = o[i][j4*4+2] * inv; w.w = o[i][j4*4+3] * inv;
            *(float4*)(op + j4*4) = w;
        }
    }
}

// ---------------------------------------------------------------------------
extern "C" void kernel_launch(void* const* d_in, const int* in_sizes, int n_in,
                              void* d_out, int out_size)
{
    (void)in_sizes; (void)n_in; (void)out_size;
    const float* hidden = (const float*)d_in[0];
    // d_in[1] = attention_mask — analytic (causal + sliding window), unused
    const float* cosb = (const float*)d_in[2];
    const float* sinb = (const float*)d_in[3];
    const float* Wq = (const float*)d_in[4];
    const float* Wk = (const float*)d_in[5];
    const float* Wv = (const float*)d_in[6];
    const float* Wo = (const float*)d_in[7];
    const float* qw = (const float*)d_in[8];
    const float* kw = (const float*)d_in[9];
    float* out = (float*)d_out;

    float *qp, *kp, *vp, *aop;
    cudaGetSymbolAddress((void**)&qp,  g_q);
    cudaGetSymbolAddress((void**)&kp,  g_k);
    cudaGetSymbolAddress((void**)&vp,  g_v);
    cudaGetSymbolAddress((void**)&aop, g_ao);

    // 1) QKV projections
    sgemm_nt<<<dim3(QCOLS/128,  MROWS/128), 256>>>(hidden, Wq, qp, MROWS, QCOLS,  HH);
    sgemm_nt<<<dim3(KVCOLS/128, MROWS/128), 256>>>(hidden, Wk, kp, MROWS, KVCOLS, HH);
    sgemm_nt<<<dim3(KVCOLS/128, MROWS/128), 256>>>(hidden, Wv, vp, MROWS, KVCOLS, HH);

    // 2) RMSNorm + RoPE (q,k) / RMSNorm (v), in place
    rmsrope_kernel<<<dim3(MROWS, NHQ + 2*NKV), 256>>>(cosb, sinb, qw, kw);

    // 3) sliding-window flash attention
    attn_kernel<<<dim3(SS/64, NHQ, BB), 256>>>();

    // 4) output projection -> d_out
    sgemm_nt<<<dim3(HH/128, MROWS/128), 256>>>(aop, Wo, out, MROWS, HH, QCOLS);
}

// round 3
// speedup vs baseline: 1.5355x; 1.5355x over previous
#include <cuda_runtime.h>
#include <cuda_bf16.h>
#include <cstdint>
#include <math.h>

// Problem constants
#define BB    2
#define SS    2048
#define HH    2560
#define NHQ   8
#define NKV   4
#define DD    256
#define SWIN  1024
#define MROWS (BB*SS)          // 4096
#define QCOLS (NHQ*DD)         // 2048
#define KVCOLS (NKV*DD)        // 1024

// ---------------- scratch (allocation-free rule: device globals) ------------
__device__ float g_q [ (size_t)MROWS * QCOLS ];
__device__ float g_k [ (size_t)MROWS * KVCOLS ];
__device__ float g_v [ (size_t)MROWS * KVCOLS ];
__device__ float g_ao[ (size_t)MROWS * QCOLS ];

// split-bf16 operands
__device__ __nv_bfloat16 g_hid_h[(size_t)MROWS*HH],  g_hid_l[(size_t)MROWS*HH];
__device__ __nv_bfloat16 g_wq_h [(size_t)QCOLS*HH],  g_wq_l [(size_t)QCOLS*HH];
__device__ __nv_bfloat16 g_wk_h [(size_t)KVCOLS*HH], g_wk_l [(size_t)KVCOLS*HH];
__device__ __nv_bfloat16 g_wv_h [(size_t)KVCOLS*HH], g_wv_l [(size_t)KVCOLS*HH];
__device__ __nv_bfloat16 g_wo_h [(size_t)HH*QCOLS],  g_wo_l [(size_t)HH*QCOLS];
__device__ __nv_bfloat16 g_ao_h [(size_t)MROWS*QCOLS], g_ao_l[(size_t)MROWS*QCOLS];

// ---------------- helpers ----------------------------------------------------
__device__ __forceinline__ uint32_t smem_u32(const void* p) {
    uint32_t a;
    asm("{ .reg .u64 t; cvta.to.shared.u64 t, %1; cvt.u32.u64 %0, t; }"
        : "=r"(a) : "l"(p));
    return a;
}
__device__ __forceinline__ void ldmatrix_x4(uint32_t* r, uint32_t addr) {
    asm volatile("ldmatrix.sync.aligned.m8n8.x4.shared.b16 {%0,%1,%2,%3}, [%4];"
                 : "=r"(r[0]), "=r"(r[1]), "=r"(r[2]), "=r"(r[3]) : "r"(addr));
}
__device__ __forceinline__ void mma_bf16(float* d, const uint32_t* a,
                                         uint32_t b0, uint32_t b1) {
    asm volatile(
        "mma.sync.aligned.m16n8k16.row.col.f32.bf16.bf16.f32 "
        "{%0,%1,%2,%3}, {%4,%5,%6,%7}, {%8,%9}, {%0,%1,%2,%3};"
        : "+f"(d[0]), "+f"(d[1]), "+f"(d[2]), "+f"(d[3])
        : "r"(a[0]), "r"(a[1]), "r"(a[2]), "r"(a[3]), "r"(b0), "r"(b1));
}
__device__ __forceinline__ void cp_async16(uint32_t saddr, const void* gaddr) {
    asm volatile("cp.async.cg.shared.global [%0], [%1], 16;"
                 :: "r"(saddr), "l"(gaddr));
}

// ---------------------------------------------------------------------------
// split fp32 -> (hi, lo) bf16
// ---------------------------------------------------------------------------
__global__ void split_kernel(const float* __restrict__ src,
                             __nv_bfloat16* __restrict__ hi,
                             __nv_bfloat16* __restrict__ lo, int n4)
{
    int i = blockIdx.x * blockDim.x + threadIdx.x;
    if (i >= n4) return;
    float4 v = ((const float4*)src)[i];
    __nv_bfloat16 hx = __float2bfloat16(v.x);
    __nv_bfloat16 hy = __float2bfloat16(v.y);
    __nv_bfloat16 hz = __float2bfloat16(v.z);
    __nv_bfloat16 hw = __float2bfloat16(v.w);
    __nv_bfloat16 lx = __float2bfloat16(v.x - __bfloat162float(hx));
    __nv_bfloat16 ly = __float2bfloat16(v.y - __bfloat162float(hy));
    __nv_bfloat16 lz = __float2bfloat16(v.z - __bfloat162float(hz));
    __nv_bfloat16 lw = __float2bfloat16(v.w - __bfloat162float(hw));
    __nv_bfloat162 h01; h01.x = hx; h01.y = hy;
    __nv_bfloat162 h23; h23.x = hz; h23.y = hw;
    __nv_bfloat162 l01; l01.x = lx; l01.y = ly;
    __nv_bfloat162 l23; l23.x = lz; l23.y = lw;
    ((__nv_bfloat162*)hi)[2*i]   = h01;
    ((__nv_bfloat162*)hi)[2*i+1] = h23;
    ((__nv_bfloat162*)lo)[2*i]   = l01;
    ((__nv_bfloat162*)lo)[2*i+1] = l23;
}

// ---------------------------------------------------------------------------
// HMMA split-bf16 GEMM: C[M,N] = A[M,K] * B[N,K]^T  (both K-major)
// C ~= Ah*Bh + Ah*Bl + Al*Bh (fp32 accum) -> near-fp32 accuracy.
// CTA 128x128, BK=32, 8 warps (warp tile 64x32), cp.async double buffer.
// smem per stage: 4 tiles (Ah,Al,Bh,Bl) of 128 rows x 40 bf16 (pad) = 40960B.
// ---------------------------------------------------------------------------
#define PADK   40
#define TILE_B (128 * PADK * 2)     // 10240
#define STAGE_B (4 * TILE_B)        // 40960
#define GEMM_SMEM (2 * STAGE_B)     // 81920

__global__ void __launch_bounds__(256) gemm_split(
    const __nv_bfloat16* __restrict__ Ah, const __nv_bfloat16* __restrict__ Al,
    const __nv_bfloat16* __restrict__ Bh, const __nv_bfloat16* __restrict__ Bl,
    float* __restrict__ C, int M, int N, int K)
{
    extern __shared__ char smem[];
    const uint32_t sbase = smem_u32(smem);

    const int tid  = threadIdx.x;
    const int wid  = tid >> 5, lane = tid & 31;
    const int wm   = wid >> 2;          // 0..1  (64-row slab)
    const int wn   = wid & 3;           // 0..3  (32-col slab)
    const int m0   = blockIdx.y * 128, n0 = blockIdx.x * 128;

    const __nv_bfloat16* gb[4] = {
        Ah + (size_t)m0 * K, Al + (size_t)m0 * K,
        Bh + (size_t)n0 * K, Bl + (size_t)n0 * K };

    const int NC = K >> 5;   // K / 32

    // cp.async issue of one 32-wide K chunk into stage s
#define ISSUE(c, s) do {                                                      \
    _Pragma("unroll")                                                         \
    for (int i = 0; i < 8; i++) {                                             \
        int e    = tid + i * 256;          /* 0..2047 */                      \
        int t    = e >> 9;                                                    \
        int rem  = e & 511;                                                   \
        int row  = rem >> 2;                                                  \
        int c16  = rem & 3;                                                   \
        uint32_t sa = sbase + (s) * STAGE_B + t * TILE_B + row * (PADK*2) + c16 * 16; \
        cp_async16(sa, gb[t] + (size_t)row * K + (c) * 32 + c16 * 8);         \
    }                                                                         \
    asm volatile("cp.async.commit_group;" ::: "memory");                      \
} while (0)

    float acc[4][4][4];
#pragma unroll
    for (int i = 0; i < 4; i++)
#pragma unroll
        for (int j = 0; j < 4; j++)
#pragma unroll
            for (int r = 0; r < 4; r++) acc[i][j][r] = 0.f;

    // ldmatrix source addresses (fixed per thread, per stage offsets added later)
    // A tiles: row = (lane&15), k-half = lane>>4
    const uint32_t a_off = (uint32_t)((lane & 15) * (PADK*2) + (lane >> 4) * 16);
    // B tiles: n = (lane&7) + (lane>>4)*8, k-half = (lane>>3)&1
    const uint32_t b_off = (uint32_t)(((lane & 7) + ((lane >> 4) << 3)) * (PADK*2)
                                      + ((lane >> 3) & 1) * 16);

    ISSUE(0, 0);

    for (int c = 0; c < NC; c++) {
        const int s = c & 1;
        if (c + 1 < NC) {
            ISSUE(c + 1, (c + 1) & 1);
            asm volatile("cp.async.wait_group 1;" ::: "memory");
        } else {
            asm volatile("cp.async.wait_group 0;" ::: "memory");
        }
        __syncthreads();

        const uint32_t sAh = sbase + s * STAGE_B;
        const uint32_t sAl = sAh + TILE_B;
        const uint32_t sBh = sAh + 2 * TILE_B;
        const uint32_t sBl = sAh + 3 * TILE_B;

#pragma unroll
        for (int ks = 0; ks < 2; ks++) {           // two k16 steps in BK=32
            const uint32_t kbyte = (uint32_t)(ks * 32);   // 16 bf16 = 32B

            uint32_t ah[4][4], al[4][4];
#pragma unroll
            for (int i = 0; i < 4; i++) {
                const uint32_t ro = (uint32_t)((wm * 64 + i * 16) * (PADK*2)) + kbyte;
                ldmatrix_x4(ah[i], sAh + ro + a_off);
                ldmatrix_x4(al[i], sAl + ro + a_off);
            }
            uint32_t bh[2][4], bl[2][4];
#pragma unroll
            for (int p = 0; p < 2; p++) {
                const uint32_t ro = (uint32_t)((wn * 32 + p * 16) * (PADK*2)) + kbyte;
                ldmatrix_x4(bh[p], sBh + ro + b_off);
                ldmatrix_x4(bl[p], sBl + ro + b_off);
            }
#pragma unroll
            for (int i = 0; i < 4; i++)
#pragma unroll
                for (int j = 0; j < 4; j++) {
                    const int p = j >> 1, u = (j & 1) * 2;
                    mma_bf16(acc[i][j], ah[i], bh[p][u], bh[p][u+1]);
                    mma_bf16(acc[i][j], ah[i], bl[p][u], bl[p][u+1]);
                    mma_bf16(acc[i][j], al[i], bh[p][u], bh[p][u+1]);
                }
        }
        __syncthreads();
    }
#undef ISSUE

    // epilogue: write fp32 accumulators
    const int rbase = m0 + wm * 64 + (lane >> 2);
    const int cbase = n0 + wn * 32 + (lane & 3) * 2;
#pragma unroll
    for (int i = 0; i < 4; i++)
#pragma unroll
        for (int j = 0; j < 4; j++) {
            float* p0 = C + (size_t)(rbase + i * 16) * N + cbase + j * 8;
            float* p1 = p0 + 8 * (size_t)N;
            *(float2*)p0 = make_float2(acc[i][j][0], acc[i][j][1]);
            *(float2*)p1 = make_float2(acc[i][j][2], acc[i][j][3]);
        }
}

// ---------------------------------------------------------------------------
// RMSNorm (+ optional weight) + RoPE, in-place on g_q/g_k/g_v.
// ---------------------------------------------------------------------------
__global__ void rmsrope_kernel(const float* __restrict__ cosb,
                               const float* __restrict__ sinb,
                               const float* __restrict__ qw,
                               const float* __restrict__ kw)
{
    const int row  = blockIdx.x;
    const int part = blockIdx.y;
    const int d    = threadIdx.x;

    float* ptr;
    const float* w = nullptr;
    bool do_rope = true;
    if (part < 8) {
        ptr = g_q + (size_t)row * QCOLS + part * DD; w = qw;
    } else if (part < 12) {
        ptr = g_k + (size_t)row * KVCOLS + (part - 8) * DD; w = kw;
    } else {
        ptr = g_v + (size_t)row * KVCOLS + (part - 12) * DD; do_rope = false;
    }

    float x = ptr[d];
    __shared__ float red[8];
    float ss = x * x;
#pragma unroll
    for (int o = 16; o; o >>= 1) ss += __shfl_xor_sync(0xffffffffu, ss, o);
    if ((d & 31) == 0) red[d >> 5] = ss;
    __syncthreads();
    float tot = red[0]+red[1]+red[2]+red[3]+red[4]+red[5]+red[6]+red[7];

    float y = x * rsqrtf(tot * (1.0f / DD) + 1e-6f);
    if (w) y *= (1.0f + w[d]);

    if (do_rope) {
        __shared__ float yb[DD];
        yb[d] = y;
        __syncthreads();
        int s = row & (SS - 1);
        float c  = cosb[(size_t)s * DD + d];
        float sn = sinb[(size_t)s * DD + d];
        float other = yb[d ^ 128];
        y = (d < 128) ? (y * c - other * sn) : (y * c + other * sn);
    }
    ptr[d] = y;
}

// ---------------------------------------------------------------------------
// Sliding-window causal flash attention, fp32 SIMT (unchanged).
// ---------------------------------------------------------------------------
__global__ void __launch_bounds__(256) attn_kernel()
{
    const int qblk = blockIdx.x;
    const int h    = blockIdx.y;
    const int b    = blockIdx.z;
    const int kvh  = h >> 1;
    const int t  = threadIdx.x;
    const int ty = t >> 4, tx = t & 15;
    const int ty4 = ty * 4, tx4 = tx * 4;
    const int qs = qblk * 64;

    __shared__ float Qc[8][65];
    __shared__ float Kc[8][65];
    __shared__ float Ss[64][65];
    __shared__ float Vc[8][256];

    float o[4][16];
#pragma unroll
    for (int i = 0; i < 4; i++)
#pragma unroll
        for (int j = 0; j < 16; j++) o[i][j] = 0.f;
    float m[4] = {-1e30f, -1e30f, -1e30f, -1e30f};
    float l[4] = {0.f, 0.f, 0.f, 0.f};

    const float* qbase = g_q + ((size_t)(b * SS + qs)) * QCOLS + h * DD;
    const float* kbase = g_k + ((size_t)(b * SS)) * KVCOLS + kvh * DD;
    const float* vbase = g_v + ((size_t)(b * SS)) * KVCOLS + kvh * DD;

    int ks_min = qs - (SWIN - 1);
    if (ks_min < 0) ks_min = 0;
    const int t0 = ks_min >> 6;

    for (int kt = t0; kt <= qblk; kt++) {
        const int ks = kt << 6;

        float sacc[4][4];
#pragma unroll
        for (int i = 0; i < 4; i++)
#pragma unroll
            for (int j = 0; j < 4; j++) sacc[i][j] = 0.f;

        for (int d0 = 0; d0 < DD; d0 += 8) {
            __syncthreads();
            {
                int tt = t & 127;
                int r  = tt >> 1;
                int dd = (tt & 1) << 2;
                if (t < 128) {
                    float4 v = *(const float4*)(qbase + (size_t)r * QCOLS + d0 + dd);
                    Qc[dd+0][r] = v.x; Qc[dd+1][r] = v.y;
                    Qc[dd+2][r] = v.z; Qc[dd+3][r] = v.w;
                } else {
                    float4 v = *(const float4*)(kbase + (size_t)(ks + r) * KVCOLS + d0 + dd);
                    Kc[dd+0][r] = v.x; Kc[dd+1][r] = v.y;
                    Kc[dd+2][r] = v.z; Kc[dd+3][r] = v.w;
                }
            }
            __syncthreads();
#pragma unroll
            for (int dd = 0; dd < 8; dd++) {
                float a0 = Qc[dd][ty4+0], a1 = Qc[dd][ty4+1];
                float a2 = Qc[dd][ty4+2], a3 = Qc[dd][ty4+3];
                float b0 = Kc[dd][tx4+0], b1 = Kc[dd][tx4+1];
                float b2 = Kc[dd][tx4+2], b3 = Kc[dd][tx4+3];
                sacc[0][0] += a0*b0; sacc[0][1] += a0*b1; sacc[0][2] += a0*b2; sacc[0][3] += a0*b3;
                sacc[1][0] += a1*b0; sacc[1][1] += a1*b1; sacc[1][2] += a1*b2; sacc[1][3] += a1*b3;
                sacc[2][0] += a2*b0; sacc[2][1] += a2*b1; sacc[2][2] += a2*b2; sacc[2][3] += a2*b3;
                sacc[3][0] += a3*b0; sacc[3][1] += a3*b1; sacc[3][2] += a3*b2; sacc[3][3] += a3*b3;
            }
        }

#pragma unroll
        for (int i = 0; i < 4; i++) {
            const int qi = qs + ty4 + i;
#pragma unroll
            for (int j = 0; j < 4; j++) {
                const int kj = ks + tx4 + j;
                if (kj > qi || kj <= qi - SWIN) sacc[i][j] = -1e30f;
            }
            float mi = fmaxf(fmaxf(sacc[i][0], sacc[i][1]), fmaxf(sacc[i][2], sacc[i][3]));
#pragma unroll
            for (int off = 8; off; off >>= 1)
                mi = fmaxf(mi, __shfl_xor_sync(0xffffffffu, mi, off));
            const float mnew = fmaxf(m[i], mi);
            const float corr = __expf(m[i] - mnew);
            float rsum = 0.f;
#pragma unroll
            for (int j = 0; j < 4; j++) {
                float p = (sacc[i][j] <= -1e29f) ? 0.f : __expf(sacc[i][j] - mnew);
                Ss[ty4 + i][tx4 + j] = p;
                rsum += p;
            }
#pragma unroll
            for (int off = 8; off; off >>= 1)
                rsum += __shfl_xor_sync(0xffffffffu, rsum, off);
            l[i] = l[i] * corr + rsum;
            m[i] = mnew;
#pragma unroll
            for (int j = 0; j < 16; j++) o[i][j] *= corr;
        }

        for (int k0 = 0; k0 < 64; k0 += 8) {
            __syncthreads();
#pragma unroll
            for (int u = 0; u < 2; u++) {
                int e  = t + u * 256;
                int r  = e >> 6;
                int dd = (e & 63) << 2;
                float4 v = *(const float4*)(vbase + (size_t)(ks + k0 + r) * KVCOLS + dd);
                *(float4*)&Vc[r][dd] = v;
            }
            __syncthreads();
#pragma unroll
            for (int kk = 0; kk < 8; kk++) {
                float p0 = Ss[ty4+0][k0+kk];
                float p1 = Ss[ty4+1][k0+kk];
                float p2 = Ss[ty4+2][k0+kk];
                float p3 = Ss[ty4+3][k0+kk];
                float4 v0 = *(const float4*)&Vc[kk][tx*16 + 0];
                float4 v1 = *(const float4*)&Vc[kk][tx*16 + 4];
                float4 v2 = *(const float4*)&Vc[kk][tx*16 + 8];
                float4 v3 = *(const float4*)&Vc[kk][tx*16 + 12];
                o[0][0]+=p0*v0.x; o[0][1]+=p0*v0.y; o[0][2]+=p0*v0.z; o[0][3]+=p0*v0.w;
                o[0][4]+=p0*v1.x; o[0][5]+=p0*v1.y; o[0][6]+=p0*v1.z; o[0][7]+=p0*v1.w;
                o[0][8]+=p0*v2.x; o[0][9]+=p0*v2.y; o[0][10]+=p0*v2.z; o[0][11]+=p0*v2.w;
                o[0][12]+=p0*v3.x; o[0][13]+=p0*v3.y; o[0][14]+=p0*v3.z; o[0][15]+=p0*v3.w;
                o[1][0]+=p1*v0.x; o[1][1]+=p1*v0.y; o[1][2]+=p1*v0.z; o[1][3]+=p1*v0.w;
                o[1][4]+=p1*v1.x; o[1][5]+=p1*v1.y; o[1][6]+=p1*v1.z; o[1][7]+=p1*v1.w;
                o[1][8]+=p1*v2.x; o[1][9]+=p1*v2.y; o[1][10]+=p1*v2.z; o[1][11]+=p1*v2.w;
                o[1][12]+=p1*v3.x; o[1][13]+=p1*v3.y; o[1][14]+=p1*v3.z; o[1][15]+=p1*v3.w;
                o[2][0]+=p2*v0.x; o[2][1]+=p2*v0.y; o[2][2]+=p2*v0.z; o[2][3]+=p2*v0.w;
                o[2][4]+=p2*v1.x; o[2][5]+=p2*v1.y; o[2][6]+=p2*v1.z; o[2][7]+=p2*v1.w;
                o[2][8]+=p2*v2.x; o[2][9]+=p2*v2.y; o[2][10]+=p2*v2.z; o[2][11]+=p2*v2.w;
                o[2][12]+=p2*v3.x; o[2][13]+=p2*v3.y; o[2][14]+=p2*v3.z; o[2][15]+=p2*v3.w;
                o[3][0]+=p3*v0.x; o[3][1]+=p3*v0.y; o[3][2]+=p3*v0.z; o[3][3]+=p3*v0.w;
                o[3][4]+=p3*v1.x; o[3][5]+=p3*v1.y; o[3][6]+=p3*v1.z; o[3][7]+=p3*v1.w;
                o[3][8]+=p3*v2.x; o[3][9]+=p3*v2.y; o[3][10]+=p3*v2.z; o[3][11]+=p3*v2.w;
                o[3][12]+=p3*v3.x; o[3][13]+=p3*v3.y; o[3][14]+=p3*v3.z; o[3][15]+=p3*v3.w;
            }
        }
    }

    float* obase = g_ao + ((size_t)(b * SS + qs)) * QCOLS + h * DD;
#pragma unroll
    for (int i = 0; i < 4; i++) {
        const float inv = 1.0f / l[i];
        float* op = obase + (size_t)(ty4 + i) * QCOLS + tx * 16;
#pragma unroll
        for (int j4 = 0; j4 < 4; j4++) {
            float4 w;
            w.x = o[i][j4*4+0] * inv; w.y = o[i][j4*4+1] * inv;
            w.z = o[i][j4*4+2] * inv; w.w = o[i][j4*4+3] * inv;
            *(float4*)(op + j4*4) = w;
        }
    }
}

// ---------------------------------------------------------------------------
extern "C" void kernel_launch(void* const* d_in, const int* in_sizes, int n_in,
                              void* d_out, int out_size)
{
    (void)in_sizes; (void)n_in; (void)out_size;
    const float* hidden = (const float*)d_in[0];
    // d_in[1] = attention_mask — analytic, unused
    const float* cosb = (const float*)d_in[2];
    const float* sinb = (const float*)d_in[3];
    const float* Wq = (const float*)d_in[4];
    const float* Wk = (const float*)d_in[5];
    const float* Wv = (const float*)d_in[6];
    const float* Wo = (const float*)d_in[7];
    const float* qw = (const float*)d_in[8];
    const float* kw = (const float*)d_in[9];
    float* out = (float*)d_out;

    float *qp, *kp, *vp, *aop;
    cudaGetSymbolAddress((void**)&qp,  g_q);
    cudaGetSymbolAddress((void**)&kp,  g_k);
    cudaGetSymbolAddress((void**)&vp,  g_v);
    cudaGetSymbolAddress((void**)&aop, g_ao);
    __nv_bfloat16 *hid_h, *hid_l, *wq_h, *wq_l, *wk_h, *wk_l, *wv_h, *wv_l,
                  *wo_h, *wo_l, *ao_h, *ao_l;
    cudaGetSymbolAddress((void**)&hid_h, g_hid_h);
    cudaGetSymbolAddress((void**)&hid_l, g_hid_l);
    cudaGetSymbolAddress((void**)&wq_h,  g_wq_h);
    cudaGetSymbolAddress((void**)&wq_l,  g_wq_l);
    cudaGetSymbolAddress((void**)&wk_h,  g_wk_h);
    cudaGetSymbolAddress((void**)&wk_l,  g_wk_l);
    cudaGetSymbolAddress((void**)&wv_h,  g_wv_h);
    cudaGetSymbolAddress((void**)&wv_l,  g_wv_l);
    cudaGetSymbolAddress((void**)&wo_h,  g_wo_h);
    cudaGetSymbolAddress((void**)&wo_l,  g_wo_l);
    cudaGetSymbolAddress((void**)&ao_h,  g_ao_h);
    cudaGetSymbolAddress((void**)&ao_l,  g_ao_l);

    cudaFuncSetAttribute(gemm_split, cudaFuncAttributeMaxDynamicSharedMemorySize,
                         GEMM_SMEM);

    // 0) split fp32 -> bf16 hi/lo
    {
        int n4;
        n4 = (int)((size_t)MROWS * HH / 4);
        split_kernel<<<(n4 + 255) / 256, 256>>>(hidden, hid_h, hid_l, n4);
        n4 = (int)((size_t)QCOLS * HH / 4);
        split_kernel<<<(n4 + 255) / 256, 256>>>(Wq, wq_h, wq_l, n4);
        n4 = (int)((size_t)KVCOLS * HH / 4);
        split_kernel<<<(n4 + 255) / 256, 256>>>(Wk, wk_h, wk_l, n4);
        split_kernel<<<(n4 + 255) / 256, 256>>>(Wv, wv_h, wv_l, n4);
        n4 = (int)((size_t)HH * QCOLS / 4);
        split_kernel<<<(n4 + 255) / 256, 256>>>(Wo, wo_h, wo_l, n4);
    }

    // 1) QKV projections (HMMA split-bf16)
    gemm_split<<<dim3(QCOLS/128,  MROWS/128), 256, GEMM_SMEM>>>(
        hid_h, hid_l, wq_h, wq_l, qp, MROWS, QCOLS, HH);
    gemm_split<<<dim3(KVCOLS/128, MROWS/128), 256, GEMM_SMEM>>>(
        hid_h, hid_l, wk_h, wk_l, kp, MROWS, KVCOLS, HH);
    gemm_split<<<dim3(KVCOLS/128, MROWS/128), 256, GEMM_SMEM>>>(
        hid_h, hid_l, wv_h, wv_l, vp, MROWS, KVCOLS, HH);

    // 2) RMSNorm + RoPE
    rmsrope_kernel<<<dim3(MROWS, NHQ + 2*NKV), 256>>>(cosb, sinb, qw, kw);

    // 3) sliding-window flash attention (fp32 SIMT)
    attn_kernel<<<dim3(SS/64, NHQ, BB), 256>>>();

    // 4) split attention output, then output projection (HMMA split-bf16)
    {
        int n4 = (int)((size_t)MROWS * QCOLS / 4);
        split_kernel<<<(n4 + 255) / 256, 256>>>(aop, ao_h, ao_l, n4);
    }
    gemm_split<<<dim3(HH/128, MROWS/128), 256, GEMM_SMEM>>>(
        ao_h, ao_l, wo_h, wo_l, out, MROWS, HH, QCOLS);
}

// round 4
// speedup vs baseline: 2.8962x; 1.8862x over previous
#include <cuda_runtime.h>
#include <cuda_bf16.h>
#include <cstdint>
#include <math.h>

// Problem constants
#define BB    2
#define SS    2048
#define HH    2560
#define NHQ   8
#define NKV   4
#define DD    256
#define SWIN  1024
#define MROWS (BB*SS)          // 4096
#define QCOLS (NHQ*DD)         // 2048
#define KVCOLS (NKV*DD)        // 1024

// ---------------- scratch (allocation-free rule: device globals) ------------
__device__ float g_q [ (size_t)MROWS * QCOLS ];
__device__ float g_k [ (size_t)MROWS * KVCOLS ];
__device__ float g_v [ (size_t)MROWS * KVCOLS ];

// split-bf16 operands
__device__ __nv_bfloat16 g_hid_h[(size_t)MROWS*HH],  g_hid_l[(size_t)MROWS*HH];
__device__ __nv_bfloat16 g_wq_h [(size_t)QCOLS*HH],  g_wq_l [(size_t)QCOLS*HH];
__device__ __nv_bfloat16 g_wk_h [(size_t)KVCOLS*HH], g_wk_l [(size_t)KVCOLS*HH];
__device__ __nv_bfloat16 g_wv_h [(size_t)KVCOLS*HH], g_wv_l [(size_t)KVCOLS*HH];
__device__ __nv_bfloat16 g_wo_h [(size_t)HH*QCOLS],  g_wo_l [(size_t)HH*QCOLS];
// post-rmsnorm/rope split q/k/v for HMMA attention
__device__ __nv_bfloat16 g_qh[(size_t)MROWS*QCOLS],  g_ql[(size_t)MROWS*QCOLS];
__device__ __nv_bfloat16 g_kh[(size_t)MROWS*KVCOLS], g_kl[(size_t)MROWS*KVCOLS];
__device__ __nv_bfloat16 g_vh[(size_t)MROWS*KVCOLS], g_vl[(size_t)MROWS*KVCOLS];
// attention output split
__device__ __nv_bfloat16 g_ao_h[(size_t)MROWS*QCOLS], g_ao_l[(size_t)MROWS*QCOLS];

// ---------------- helpers ----------------------------------------------------
__device__ __forceinline__ uint32_t smem_u32(const void* p) {
    uint32_t a;
    asm("{ .reg .u64 t; cvta.to.shared.u64 t, %1; cvt.u32.u64 %0, t; }"
        : "=r"(a) : "l"(p));
    return a;
}
__device__ __forceinline__ void ldmatrix_x4(uint32_t* r, uint32_t addr) {
    asm volatile("ldmatrix.sync.aligned.m8n8.x4.shared.b16 {%0,%1,%2,%3}, [%4];"
                 : "=r"(r[0]), "=r"(r[1]), "=r"(r[2]), "=r"(r[3]) : "r"(addr));
}
__device__ __forceinline__ void ldmatrix_x4_t(uint32_t* r, uint32_t addr) {
    asm volatile("ldmatrix.sync.aligned.m8n8.x4.trans.shared.b16 {%0,%1,%2,%3}, [%4];"
                 : "=r"(r[0]), "=r"(r[1]), "=r"(r[2]), "=r"(r[3]) : "r"(addr));
}
__device__ __forceinline__ void mma_bf16(float* d, const uint32_t* a,
                                         uint32_t b0, uint32_t b1) {
    asm volatile(
        "mma.sync.aligned.m16n8k16.row.col.f32.bf16.bf16.f32 "
        "{%0,%1,%2,%3}, {%4,%5,%6,%7}, {%8,%9}, {%0,%1,%2,%3};"
        : "+f"(d[0]), "+f"(d[1]), "+f"(d[2]), "+f"(d[3])
        : "r"(a[0]), "r"(a[1]), "r"(a[2]), "r"(a[3]), "r"(b0), "r"(b1));
}
__device__ __forceinline__ void cp_async16(uint32_t saddr, const void* gaddr) {
    asm volatile("cp.async.cg.shared.global [%0], [%1], 16;"
                 :: "r"(saddr), "l"(gaddr));
}
__device__ __forceinline__ uint32_t pack_bf16x2(float a, float b) {
    __nv_bfloat162 t;
    t.x = __float2bfloat16(a); t.y = __float2bfloat16(b);
    return *(uint32_t*)&t;
}

// ---------------------------------------------------------------------------
// split fp32 -> (hi, lo) bf16
// ---------------------------------------------------------------------------
__global__ void split_kernel(const float* __restrict__ src,
                             __nv_bfloat16* __restrict__ hi,
                             __nv_bfloat16* __restrict__ lo, int n4)
{
    int i = blockIdx.x * blockDim.x + threadIdx.x;
    if (i >= n4) return;
    float4 v = ((const float4*)src)[i];
    __nv_bfloat16 hx = __float2bfloat16(v.x);
    __nv_bfloat16 hy = __float2bfloat16(v.y);
    __nv_bfloat16 hz = __float2bfloat16(v.z);
    __nv_bfloat16 hw = __float2bfloat16(v.w);
    __nv_bfloat16 lx = __float2bfloat16(v.x - __bfloat162float(hx));
    __nv_bfloat16 ly = __float2bfloat16(v.y - __bfloat162float(hy));
    __nv_bfloat16 lz = __float2bfloat16(v.z - __bfloat162float(hz));
    __nv_bfloat16 lw = __float2bfloat16(v.w - __bfloat162float(hw));
    __nv_bfloat162 h01; h01.x = hx; h01.y = hy;
    __nv_bfloat162 h23; h23.x = hz; h23.y = hw;
    __nv_bfloat162 l01; l01.x = lx; l01.y = ly;
    __nv_bfloat162 l23; l23.x = lz; l23.y = lw;
    ((__nv_bfloat162*)hi)[2*i]   = h01;
    ((__nv_bfloat162*)hi)[2*i+1] = h23;
    ((__nv_bfloat162*)lo)[2*i]   = l01;
    ((__nv_bfloat162*)lo)[2*i+1] = l23;
}

// ---------------------------------------------------------------------------
// HMMA split-bf16 GEMM (unchanged, proven): C = A * B^T, K-major operands
// ---------------------------------------------------------------------------
#define PADK   40
#define TILE_B (128 * PADK * 2)
#define STAGE_B (4 * TILE_B)
#define GEMM_SMEM (2 * STAGE_B)

__global__ void __launch_bounds__(256) gemm_split(
    const __nv_bfloat16* __restrict__ Ah, const __nv_bfloat16* __restrict__ Al,
    const __nv_bfloat16* __restrict__ Bh, const __nv_bfloat16* __restrict__ Bl,
    float* __restrict__ C, int M, int N, int K)
{
    extern __shared__ char smem[];
    const uint32_t sbase = smem_u32(smem);

    const int tid  = threadIdx.x;
    const int wid  = tid >> 5, lane = tid & 31;
    const int wm   = wid >> 2;
    const int wn   = wid & 3;
    const int m0   = blockIdx.y * 128, n0 = blockIdx.x * 128;

    const __nv_bfloat16* gb[4] = {
        Ah + (size_t)m0 * K, Al + (size_t)m0 * K,
        Bh + (size_t)n0 * K, Bl + (size_t)n0 * K };

    const int NC = K >> 5;

#define ISSUE(c, s) do {                                                      \
    _Pragma("unroll")                                                         \
    for (int i = 0; i < 8; i++) {                                             \
        int e    = tid + i * 256;                                             \
        int t    = e >> 9;                                                    \
        int rem  = e & 511;                                                   \
        int row  = rem >> 2;                                                  \
        int c16  = rem & 3;                                                   \
        uint32_t sa = sbase + (s) * STAGE_B + t * TILE_B + row * (PADK*2) + c16 * 16; \
        cp_async16(sa, gb[t] + (size_t)row * K + (c) * 32 + c16 * 8);         \
    }                                                                         \
    asm volatile("cp.async.commit_group;" ::: "memory");                      \
} while (0)

    float acc[4][4][4];
#pragma unroll
    for (int i = 0; i < 4; i++)
#pragma unroll
        for (int j = 0; j < 4; j++)
#pragma unroll
            for (int r = 0; r < 4; r++) acc[i][j][r] = 0.f;

    const uint32_t a_off = (uint32_t)((lane & 15) * (PADK*2) + (lane >> 4) * 16);
    const uint32_t b_off = (uint32_t)(((lane & 7) + ((lane >> 4) << 3)) * (PADK*2)
                                      + ((lane >> 3) & 1) * 16);

    ISSUE(0, 0);

    for (int c = 0; c < NC; c++) {
        const int s = c & 1;
        if (c + 1 < NC) {
            ISSUE(c + 1, (c + 1) & 1);
            asm volatile("cp.async.wait_group 1;" ::: "memory");
        } else {
            asm volatile("cp.async.wait_group 0;" ::: "memory");
        }
        __syncthreads();

        const uint32_t sAh = sbase + s * STAGE_B;
        const uint32_t sAl = sAh + TILE_B;
        const uint32_t sBh = sAh + 2 * TILE_B;
        const uint32_t sBl = sAh + 3 * TILE_B;

#pragma unroll
        for (int ks = 0; ks < 2; ks++) {
            const uint32_t kbyte = (uint32_t)(ks * 32);

            uint32_t ah[4][4], al[4][4];
#pragma unroll
            for (int i = 0; i < 4; i++) {
                const uint32_t ro = (uint32_t)((wm * 64 + i * 16) * (PADK*2)) + kbyte;
                ldmatrix_x4(ah[i], sAh + ro + a_off);
                ldmatrix_x4(al[i], sAl + ro + a_off);
            }
            uint32_t bh[2][4], bl[2][4];
#pragma unroll
            for (int p = 0; p < 2; p++) {
                const uint32_t ro = (uint32_t)((wn * 32 + p * 16) * (PADK*2)) + kbyte;
                ldmatrix_x4(bh[p], sBh + ro + b_off);
                ldmatrix_x4(bl[p], sBl + ro + b_off);
            }
#pragma unroll
            for (int i = 0; i < 4; i++)
#pragma unroll
                for (int j = 0; j < 4; j++) {
                    const int p = j >> 1, u = (j & 1) * 2;
                    mma_bf16(acc[i][j], ah[i], bh[p][u], bh[p][u+1]);
                    mma_bf16(acc[i][j], ah[i], bl[p][u], bl[p][u+1]);
                    mma_bf16(acc[i][j], al[i], bh[p][u], bh[p][u+1]);
                }
        }
        __syncthreads();
    }
#undef ISSUE

    const int rbase = m0 + wm * 64 + (lane >> 2);
    const int cbase = n0 + wn * 32 + (lane & 3) * 2;
#pragma unroll
    for (int i = 0; i < 4; i++)
#pragma unroll
        for (int j = 0; j < 4; j++) {
            float* p0 = C + (size_t)(rbase + i * 16) * N + cbase + j * 8;
            float* p1 = p0 + 8 * (size_t)N;
            *(float2*)p0 = make_float2(acc[i][j][0], acc[i][j][1]);
            *(float2*)p1 = make_float2(acc[i][j][2], acc[i][j][3]);
        }
}

// ---------------------------------------------------------------------------
// RMSNorm (+ optional weight) + RoPE; reads fp32 q/k/v, writes bf16 hi/lo.
// ---------------------------------------------------------------------------
__global__ void rmsrope_kernel(const float* __restrict__ cosb,
                               const float* __restrict__ sinb,
                               const float* __restrict__ qw,
                               const float* __restrict__ kw)
{
    const int row  = blockIdx.x;
    const int part = blockIdx.y;
    const int d    = threadIdx.x;

    const float* ptr;
    __nv_bfloat16 *hp, *lp;
    const float* w = nullptr;
    bool do_rope = true;
    if (part < 8) {
        size_t off = (size_t)row * QCOLS + part * DD;
        ptr = g_q + off; hp = g_qh + off; lp = g_ql + off; w = qw;
    } else if (part < 12) {
        size_t off = (size_t)row * KVCOLS + (part - 8) * DD;
        ptr = g_k + off; hp = g_kh + off; lp = g_kl + off; w = kw;
    } else {
        size_t off = (size_t)row * KVCOLS + (part - 12) * DD;
        ptr = g_v + off; hp = g_vh + off; lp = g_vl + off; do_rope = false;
    }

    float x = ptr[d];
    __shared__ float red[8];
    float ss = x * x;
#pragma unroll
    for (int o = 16; o; o >>= 1) ss += __shfl_xor_sync(0xffffffffu, ss, o);
    if ((d & 31) == 0) red[d >> 5] = ss;
    __syncthreads();
    float tot = red[0]+red[1]+red[2]+red[3]+red[4]+red[5]+red[6]+red[7];

    float y = x * rsqrtf(tot * (1.0f / DD) + 1e-6f);
    if (w) y *= (1.0f + w[d]);

    if (do_rope) {
        __shared__ float yb[DD];
        yb[d] = y;
        __syncthreads();
        int s = row & (SS - 1);
        float c  = cosb[(size_t)s * DD + d];
        float sn = sinb[(size_t)s * DD + d];
        float other = yb[d ^ 128];
        y = (d < 128) ? (y * c - other * sn) : (y * c + other * sn);
    }
    __nv_bfloat16 h = __float2bfloat16(y);
    hp[d] = h;
    lp[d] = __float2bfloat16(y - __bfloat162float(h));
}

// ---------------------------------------------------------------------------
// HMMA split-bf16 sliding-window flash attention.
// BQ=128 (8 warps x 16 rows), BK=64, D=256. 3-pass hi/lo for QK^T and PV.
// smem: Qh/Ql resident [128][264] bf16 each; K/V share a [64][264]x2 buffer.
// ---------------------------------------------------------------------------
#define QSTR 528                     // 264 bf16 = 528B row stride
#define QTILE (128 * QSTR)           // 67584
#define KTILE (64 * QSTR)            // 33792
#define ATT_SMEM (2*QTILE + 2*KTILE) // 202752

__global__ void __launch_bounds__(256, 1) attn_hmma()
{
    extern __shared__ char smem[];
    const uint32_t sb   = smem_u32(smem);
    const uint32_t qh_s = sb;
    const uint32_t ql_s = sb + QTILE;
    const uint32_t kv_s = sb + 2 * QTILE;   // [h tile][l tile]

    const int qblk = gridDim.x - 1 - blockIdx.x;   // heavy CTAs first
    const int h    = blockIdx.y;
    const int b    = blockIdx.z;
    const int kvh  = h >> 1;
    const int tid  = threadIdx.x;
    const int wid  = tid >> 5, lane = tid & 31;
    const int wrow = wid * 16;
    const int qs   = qblk * 128;

    // ---- Q resident load (hi & lo) ----
    {
        const __nv_bfloat16* qsrc[2] = {
            g_qh + (size_t)(b*SS + qs) * QCOLS + h * DD,
            g_ql + (size_t)(b*SS + qs) * QCOLS + h * DD };
#pragma unroll
        for (int i = 0; i < 32; i++) {
            int e = tid + i * 256;          // 0..8191
            int arr = e >> 12;
            int rem = e & 4095;
            int row = rem >> 5, c16 = rem & 31;
            cp_async16((arr ? ql_s : qh_s) + row * QSTR + c16 * 16,
                       qsrc[arr] + (size_t)row * QCOLS + c16 * 8);
        }
        asm volatile("cp.async.commit_group;" ::: "memory");
    }

    float out[32][4];
#pragma unroll
    for (int nt = 0; nt < 32; nt++)
#pragma unroll
        for (int r = 0; r < 4; r++) out[nt][r] = 0.f;
    float mrow[2] = {-1e30f, -1e30f};
    float lrow[2] = {0.f, 0.f};

    const __nv_bfloat16* khg = g_kh + (size_t)(b*SS) * KVCOLS + kvh * DD;
    const __nv_bfloat16* klg = g_kl + (size_t)(b*SS) * KVCOLS + kvh * DD;
    const __nv_bfloat16* vhg = g_vh + (size_t)(b*SS) * KVCOLS + kvh * DD;
    const __nv_bfloat16* vlg = g_vl + (size_t)(b*SS) * KVCOLS + kvh * DD;

    int ksmin = qs - (SWIN - 1);
    if (ksmin < 0) ksmin = 0;
    const int t0 = ksmin >> 6;
    const int t1 = (qs + 127) >> 6;

    const uint32_t a_off = (uint32_t)((wrow + (lane & 15)) * QSTR + (lane >> 4) * 16);
    const uint32_t b_off = (uint32_t)(((lane & 7) + ((lane >> 4) << 3)) * QSTR
                                      + ((lane >> 3) & 1) * 16);
    // trans B-frag (V): key row = lane&15, d-block = (lane>>4)*8
    const uint32_t v_off = (uint32_t)((lane & 15) * QSTR + (lane >> 4) * 16);

    const int lg = lane >> 2;           // row within m16 tile
    const int lc = (lane & 3) * 2;      // col pair base

    for (int kt = t0; kt <= t1; kt++) {
        const int ks = kt << 6;

        // ---- load K tile (hi, lo) ----
#pragma unroll
        for (int i = 0; i < 16; i++) {
            int e = tid + i * 256;          // 0..4095
            int arr = e >> 11;
            int rem = e & 2047;
            int row = rem >> 5, c16 = rem & 31;
            cp_async16(kv_s + arr * KTILE + row * QSTR + c16 * 16,
                       (arr ? klg : khg) + (size_t)(ks + row) * KVCOLS + c16 * 8);
        }
        asm volatile("cp.async.commit_group;" ::: "memory");
        asm volatile("cp.async.wait_group 0;" ::: "memory");
        __syncthreads();

        // ---- S = Q K^T (split 3-pass) ----
        float sacc[8][4];
#pragma unroll
        for (int j = 0; j < 8; j++)
#pragma unroll
            for (int r = 0; r < 4; r++) sacc[j][r] = 0.f;

#pragma unroll
        for (int ks16 = 0; ks16 < 16; ks16++) {
            uint32_t qf_h[4], qf_l[4];
            ldmatrix_x4(qf_h, qh_s + a_off + ks16 * 32);
            ldmatrix_x4(qf_l, ql_s + a_off + ks16 * 32);
#pragma unroll
            for (int jp = 0; jp < 4; jp++) {
                uint32_t kf_h[4], kf_l[4];
                const uint32_t ro = (uint32_t)(jp * 16 * QSTR) + ks16 * 32;
                ldmatrix_x4(kf_h, kv_s + ro + b_off);
                ldmatrix_x4(kf_l, kv_s + KTILE + ro + b_off);
#pragma unroll
                for (int u = 0; u < 2; u++) {
                    const int j = jp * 2 + u;
                    mma_bf16(sacc[j], qf_h, kf_h[u*2], kf_h[u*2+1]);
                    mma_bf16(sacc[j], qf_h, kf_l[u*2], kf_l[u*2+1]);
                    mma_bf16(sacc[j], qf_l, kf_h[u*2], kf_h[u*2+1]);
                }
            }
        }

        // ---- mask + online softmax (warp-local) ----
        uint32_t ph[8][2], pl[8][2];
#pragma unroll
        for (int g = 0; g < 2; g++) {
            const int qi = qs + wrow + lg + g * 8;
            float mloc = -1e30f;
#pragma unroll
            for (int j = 0; j < 8; j++)
#pragma unroll
                for (int e = 0; e < 2; e++) {
                    const int kj = ks + j * 8 + lc + e;
                    float s = sacc[j][g*2+e];
                    if (kj > qi || kj <= qi - SWIN) s = -1e30f;
                    sacc[j][g*2+e] = s;
                    mloc = fmaxf(mloc, s);
                }
            mloc = fmaxf(mloc, __shfl_xor_sync(0xffffffffu, mloc, 1));
            mloc = fmaxf(mloc, __shfl_xor_sync(0xffffffffu, mloc, 2));
            const float mnew = fmaxf(mrow[g], mloc);
            const float corr = __expf(mrow[g] - mnew);
            float ls = 0.f;
#pragma unroll
            for (int j = 0; j < 8; j++)
#pragma unroll
                for (int e = 0; e < 2; e++) {
                    float s = sacc[j][g*2+e];
                    float p = (s <= -1e29f) ? 0.f : __expf(s - mnew);
                    sacc[j][g*2+e] = p;
                    ls += p;
                }
            ls += __shfl_xor_sync(0xffffffffu, ls, 1);
            ls += __shfl_xor_sync(0xffffffffu, ls, 2);
            lrow[g] = lrow[g] * corr + ls;
            mrow[g] = mnew;
#pragma unroll
            for (int nt = 0; nt < 32; nt++) {
                out[nt][g*2+0] *= corr;
                out[nt][g*2+1] *= corr;
            }
        }
        // pack P to bf16 hi/lo A-fragments (register repack)
#pragma unroll
        for (int j = 0; j < 8; j++)
#pragma unroll
            for (int g = 0; g < 2; g++) {
                float v0 = sacc[j][g*2+0], v1 = sacc[j][g*2+1];
                __nv_bfloat16 h0 = __float2bfloat16(v0);
                __nv_bfloat16 h1 = __float2bfloat16(v1);
                __nv_bfloat162 hh; hh.x = h0; hh.y = h1;
                ph[j][g] = *(uint32_t*)&hh;
                pl[j][g] = pack_bf16x2(v0 - __bfloat162float(h0),
                                       v1 - __bfloat162float(h1));
            }

        __syncthreads();   // all warps done reading K smem

        // ---- load V tile (hi, lo) into the same buffer ----
#pragma unroll
        for (int i = 0; i < 16; i++) {
            int e = tid + i * 256;
            int arr = e >> 11;
            int rem = e & 2047;
            int row = rem >> 5, c16 = rem & 31;
            cp_async16(kv_s + arr * KTILE + row * QSTR + c16 * 16,
                       (arr ? vlg : vhg) + (size_t)(ks + row) * KVCOLS + c16 * 8);
        }
        asm volatile("cp.async.commit_group;" ::: "memory");
        asm volatile("cp.async.wait_group 0;" ::: "memory");
        __syncthreads();

        // ---- O += P V (split 3-pass) ----
#pragma unroll
        for (int s = 0; s < 4; s++) {
            uint32_t aph[4] = { ph[2*s][0], ph[2*s][1], ph[2*s+1][0], ph[2*s+1][1] };
            uint32_t apl[4] = { pl[2*s][0], pl[2*s][1], pl[2*s+1][0], pl[2*s+1][1] };
            const uint32_t krow = (uint32_t)(s * 16 * QSTR);
#pragma unroll
            for (int np = 0; np < 16; np++) {
                uint32_t vf_h[4], vf_l[4];
                const uint32_t vo = krow + (uint32_t)(np * 32) + v_off;
                ldmatrix_x4_t(vf_h, kv_s + vo);
                ldmatrix_x4_t(vf_l, kv_s + KTILE + vo);
#pragma unroll
                for (int u = 0; u < 2; u++) {
                    const int nt = np * 2 + u;
                    mma_bf16(out[nt], aph, vf_h[u*2], vf_h[u*2+1]);
                    mma_bf16(out[nt], apl, vf_h[u*2], vf_h[u*2+1]);
                    mma_bf16(out[nt], aph, vf_l[u*2], vf_l[u*2+1]);
                }
            }
        }
        __syncthreads();   // PV done before next tile overwrites K/V buffer
    }

    // ---- epilogue: divide by l, split to bf16 hi/lo, store ----
#pragma unroll
    for (int g = 0; g < 2; g++) {
        const float inv = 1.0f / lrow[g];
        const int row = qs + wrow + lg + g * 8;
        __nv_bfloat16* oh = g_ao_h + (size_t)(b*SS + row) * QCOLS + h * DD + lc;
        __nv_bfloat16* ol = g_ao_l + (size_t)(b*SS + row) * QCOLS + h * DD + lc;
#pragma unroll
        for (int nt = 0; nt < 32; nt++) {
            float v0 = out[nt][g*2+0] * inv;
            float v1 = out[nt][g*2+1] * inv;
            __nv_bfloat16 h0 = __float2bfloat16(v0);
            __nv_bfloat16 h1 = __float2bfloat16(v1);
            __nv_bfloat162 hh; hh.x = h0; hh.y = h1;
            *(uint32_t*)(oh + nt*8) = *(uint32_t*)&hh;
            *(uint32_t*)(ol + nt*8) = pack_bf16x2(v0 - __bfloat162float(h0),
                                                  v1 - __bfloat162float(h1));
        }
    }
}

// ---------------------------------------------------------------------------
extern "C" void kernel_launch(void* const* d_in, const int* in_sizes, int n_in,
                              void* d_out, int out_size)
{
    (void)in_sizes; (void)n_in; (void)out_size;
    const float* hidden = (const float*)d_in[0];
    // d_in[1] = attention_mask — analytic, unused
    const float* cosb = (const float*)d_in[2];
    const float* sinb = (const float*)d_in[3];
    const float* Wq = (const float*)d_in[4];
    const float* Wk = (const float*)d_in[5];
    const float* Wv = (const float*)d_in[6];
    const float* Wo = (const float*)d_in[7];
    const float* qw = (const float*)d_in[8];
    const float* kw = (const float*)d_in[9];
    float* out = (float*)d_out;

    float *qp, *kp, *vp;
    cudaGetSymbolAddress((void**)&qp,  g_q);
    cudaGetSymbolAddress((void**)&kp,  g_k);
    cudaGetSymbolAddress((void**)&vp,  g_v);
    __nv_bfloat16 *hid_h, *hid_l, *wq_h, *wq_l, *wk_h, *wk_l, *wv_h, *wv_l,
                  *wo_h, *wo_l, *ao_h, *ao_l;
    cudaGetSymbolAddress((void**)&hid_h, g_hid_h);
    cudaGetSymbolAddress((void**)&hid_l, g_hid_l);
    cudaGetSymbolAddress((void**)&wq_h,  g_wq_h);
    cudaGetSymbolAddress((void**)&wq_l,  g_wq_l);
    cudaGetSymbolAddress((void**)&wk_h,  g_wk_h);
    cudaGetSymbolAddress((void**)&wk_l,  g_wk_l);
    cudaGetSymbolAddress((void**)&wv_h,  g_wv_h);
    cudaGetSymbolAddress((void**)&wv_l,  g_wv_l);
    cudaGetSymbolAddress((void**)&wo_h,  g_wo_h);
    cudaGetSymbolAddress((void**)&wo_l,  g_wo_l);
    cudaGetSymbolAddress((void**)&ao_h,  g_ao_h);
    cudaGetSymbolAddress((void**)&ao_l,  g_ao_l);

    cudaFuncSetAttribute(gemm_split, cudaFuncAttributeMaxDynamicSharedMemorySize,
                         GEMM_SMEM);
    cudaFuncSetAttribute(attn_hmma, cudaFuncAttributeMaxDynamicSharedMemorySize,
                         ATT_SMEM);

    // 0) split fp32 -> bf16 hi/lo (hidden + weights)
    {
        int n4;
        n4 = (int)((size_t)MROWS * HH / 4);
        split_kernel<<<(n4 + 255) / 256, 256>>>(hidden, hid_h, hid_l, n4);
        n4 = (int)((size_t)QCOLS * HH / 4);
        split_kernel<<<(n4 + 255) / 256, 256>>>(Wq, wq_h, wq_l, n4);
        n4 = (int)((size_t)KVCOLS * HH / 4);
        split_kernel<<<(n4 + 255) / 256, 256>>>(Wk, wk_h, wk_l, n4);
        split_kernel<<<(n4 + 255) / 256, 256>>>(Wv, wv_h, wv_l, n4);
        n4 = (int)((size_t)HH * QCOLS / 4);
        split_kernel<<<(n4 + 255) / 256, 256>>>(Wo, wo_h, wo_l, n4);
    }

    // 1) QKV projections (HMMA split-bf16) -> fp32 q/k/v
    gemm_split<<<dim3(QCOLS/128,  MROWS/128), 256, GEMM_SMEM>>>(
        hid_h, hid_l, wq_h, wq_l, qp, MROWS, QCOLS, HH);
    gemm_split<<<dim3(KVCOLS/128, MROWS/128), 256, GEMM_SMEM>>>(
        hid_h, hid_l, wk_h, wk_l, kp, MROWS, KVCOLS, HH);
    gemm_split<<<dim3(KVCOLS/128, MROWS/128), 256, GEMM_SMEM>>>(
        hid_h, hid_l, wv_h, wv_l, vp, MROWS, KVCOLS, HH);

    // 2) RMSNorm + RoPE -> bf16 hi/lo q/k/v
    rmsrope_kernel<<<dim3(MROWS, NHQ + 2*NKV), 256>>>(cosb, sinb, qw, kw);

    // 3) HMMA sliding-window flash attention -> bf16 hi/lo ao
    attn_hmma<<<dim3(SS/128, NHQ, BB), 256, ATT_SMEM>>>();

    // 4) output projection (HMMA split-bf16) -> fp32 d_out
    gemm_split<<<dim3(HH/128, MROWS/128), 256, GEMM_SMEM>>>(
        ao_h, ao_l, wo_h, wo_l, out, MROWS, HH, QCOLS);
}

// round 5
// speedup vs baseline: 4.0081x; 1.3839x over previous
#include <cuda_runtime.h>
#include <cuda_fp16.h>
#include <cstdint>
#include <math.h>

// Problem constants
#define BB    2
#define SS    2048
#define HH    2560
#define NHQ   8
#define NKV   4
#define DD    256
#define SWIN  1024
#define MROWS (BB*SS)          // 4096
#define QCOLS (NHQ*DD)         // 2048
#define KVCOLS (NKV*DD)        // 1024

// ---------------- scratch (allocation-free rule: device globals) ------------
__device__ float g_q [ (size_t)MROWS * QCOLS ];
__device__ float g_k [ (size_t)MROWS * KVCOLS ];
__device__ float g_v [ (size_t)MROWS * KVCOLS ];

// split-fp16 operands
__device__ __half g_hid_h[(size_t)MROWS*HH],  g_hid_l[(size_t)MROWS*HH];
__device__ __half g_wq_h [(size_t)QCOLS*HH],  g_wq_l [(size_t)QCOLS*HH];
__device__ __half g_wk_h [(size_t)KVCOLS*HH], g_wk_l [(size_t)KVCOLS*HH];
__device__ __half g_wv_h [(size_t)KVCOLS*HH], g_wv_l [(size_t)KVCOLS*HH];
__device__ __half g_wo_h [(size_t)HH*QCOLS],  g_wo_l [(size_t)HH*QCOLS];
// post-rmsnorm/rope q/k (hi/lo) and v (hi only)
__device__ __half g_qh[(size_t)MROWS*QCOLS],  g_ql[(size_t)MROWS*QCOLS];
__device__ __half g_kh[(size_t)MROWS*KVCOLS], g_kl[(size_t)MROWS*KVCOLS];
__device__ __half g_vh[(size_t)MROWS*KVCOLS];
// attention output (hi only; Wo GEMM keeps the Wo residual pass instead)
__device__ __half g_ao_h[(size_t)MROWS*QCOLS];

// ---------------- helpers ----------------------------------------------------
__device__ __forceinline__ uint32_t smem_u32(const void* p) {
    uint32_t a;
    asm("{ .reg .u64 t; cvta.to.shared.u64 t, %1; cvt.u32.u64 %0, t; }"
        : "=r"(a) : "l"(p));
    return a;
}
__device__ __forceinline__ void ldmatrix_x4(uint32_t* r, uint32_t addr) {
    asm volatile("ldmatrix.sync.aligned.m8n8.x4.shared.b16 {%0,%1,%2,%3}, [%4];"
                 : "=r"(r[0]), "=r"(r[1]), "=r"(r[2]), "=r"(r[3]) : "r"(addr));
}
__device__ __forceinline__ void ldmatrix_x4_t(uint32_t* r, uint32_t addr) {
    asm volatile("ldmatrix.sync.aligned.m8n8.x4.trans.shared.b16 {%0,%1,%2,%3}, [%4];"
                 : "=r"(r[0]), "=r"(r[1]), "=r"(r[2]), "=r"(r[3]) : "r"(addr));
}
__device__ __forceinline__ void mma_f16(float* d, const uint32_t* a,
                                        uint32_t b0, uint32_t b1) {
    asm volatile(
        "mma.sync.aligned.m16n8k16.row.col.f32.f16.f16.f32 "
        "{%0,%1,%2,%3}, {%4,%5,%6,%7}, {%8,%9}, {%0,%1,%2,%3};"
        : "+f"(d[0]), "+f"(d[1]), "+f"(d[2]), "+f"(d[3])
        : "r"(a[0]), "r"(a[1]), "r"(a[2]), "r"(a[3]), "r"(b0), "r"(b1));
}
__device__ __forceinline__ void cp_async16(uint32_t saddr, const void* gaddr) {
    asm volatile("cp.async.cg.shared.global [%0], [%1], 16;"
                 :: "r"(saddr), "l"(gaddr));
}
__device__ __forceinline__ uint32_t pack_h2(float a, float b) {
    __half2 t; t.x = __float2half(a); t.y = __float2half(b);
    return *(uint32_t*)&t;
}

// ---------------------------------------------------------------------------
// split fp32 -> (hi, lo) fp16
// ---------------------------------------------------------------------------
__global__ void split_kernel(const float* __restrict__ src,
                             __half* __restrict__ hi,
                             __half* __restrict__ lo, int n4)
{
    int i = blockIdx.x * blockDim.x + threadIdx.x;
    if (i >= n4) return;
    float4 v = ((const float4*)src)[i];
    __half hx = __float2half(v.x), hy = __float2half(v.y);
    __half hz = __float2half(v.z), hw = __float2half(v.w);
    __half lx = __float2half(v.x - __half2float(hx));
    __half ly = __float2half(v.y - __half2float(hy));
    __half lz = __float2half(v.z - __half2float(hz));
    __half lw = __float2half(v.w - __half2float(hw));
    __half2 h01; h01.x = hx; h01.y = hy;
    __half2 h23; h23.x = hz; h23.y = hw;
    __half2 l01; l01.x = lx; l01.y = ly;
    __half2 l23; l23.x = lz; l23.y = lw;
    ((__half2*)hi)[2*i]   = h01;
    ((__half2*)hi)[2*i+1] = h23;
    ((__half2*)lo)[2*i]   = l01;
    ((__half2*)lo)[2*i+1] = l23;
}

// ---------------------------------------------------------------------------
// Fused QKV projection, 3-pass split-fp16 HMMA:
//   [q|k|v](M, n) = hidden(M, K) * W[q|k|v](n, K)^T ,  K = HH
// grid.x = 32 (n-blocks over 4096 combined cols), grid.y = 32 (m-blocks).
// ---------------------------------------------------------------------------
#define PADK   40
#define TILE_B (128 * PADK * 2)
#define STAGE3_B (4 * TILE_B)
#define QKV_SMEM (2 * STAGE3_B)     // 81920

__global__ void __launch_bounds__(256) gemm_qkv(
    const __half* __restrict__ Ah, const __half* __restrict__ Al,
    const __half* __restrict__ wqh, const __half* __restrict__ wql,
    const __half* __restrict__ wkh, const __half* __restrict__ wkl,
    const __half* __restrict__ wvh, const __half* __restrict__ wvl,
    float* __restrict__ qout, float* __restrict__ kout, float* __restrict__ vout)
{
    extern __shared__ char smem[];
    const uint32_t sbase = smem_u32(smem);
    const int K = HH;

    const int tid  = threadIdx.x;
    const int wid  = tid >> 5, lane = tid & 31;
    const int wm   = wid >> 2;
    const int wn   = wid & 3;
    const int m0   = blockIdx.y * 128;
    const int n0g  = blockIdx.x * 128;

    const __half *Bh, *Bl;
    float* C;
    int n0, NN;
    if (n0g < QCOLS)              { Bh = wqh; Bl = wql; C = qout; n0 = n0g;          NN = QCOLS; }
    else if (n0g < QCOLS+KVCOLS)  { Bh = wkh; Bl = wkl; C = kout; n0 = n0g - QCOLS;  NN = KVCOLS; }
    else                          { Bh = wvh; Bl = wvl; C = vout; n0 = n0g - 3072;   NN = KVCOLS; }

    const __half* gb[4] = {
        Ah + (size_t)m0 * K, Al + (size_t)m0 * K,
        Bh + (size_t)n0 * K, Bl + (size_t)n0 * K };

    const int NC = K >> 5;

#define ISSUE3(c, s) do {                                                     \
    _Pragma("unroll")                                                         \
    for (int i = 0; i < 8; i++) {                                             \
        int e    = tid + i * 256;                                             \
        int t    = e >> 9;                                                    \
        int rem  = e & 511;                                                   \
        int row  = rem >> 2;                                                  \
        int c16  = rem & 3;                                                   \
        uint32_t sa = sbase + (s) * STAGE3_B + t * TILE_B + row * (PADK*2) + c16 * 16; \
        cp_async16(sa, gb[t] + (size_t)row * K + (c) * 32 + c16 * 8);         \
    }                                                                         \
    asm volatile("cp.async.commit_group;" ::: "memory");                      \
} while (0)

    float acc[4][4][4];
#pragma unroll
    for (int i = 0; i < 4; i++)
#pragma unroll
        for (int j = 0; j < 4; j++)
#pragma unroll
            for (int r = 0; r < 4; r++) acc[i][j][r] = 0.f;

    const uint32_t a_off = (uint32_t)((lane & 15) * (PADK*2) + (lane >> 4) * 16);
    const uint32_t b_off = (uint32_t)(((lane & 7) + ((lane >> 4) << 3)) * (PADK*2)
                                      + ((lane >> 3) & 1) * 16);

    ISSUE3(0, 0);

    for (int c = 0; c < NC; c++) {
        const int s = c & 1;
        if (c + 1 < NC) {
            ISSUE3(c + 1, (c + 1) & 1);
            asm volatile("cp.async.wait_group 1;" ::: "memory");
        } else {
            asm volatile("cp.async.wait_group 0;" ::: "memory");
        }
        __syncthreads();

        const uint32_t sAh = sbase + s * STAGE3_B;
        const uint32_t sAl = sAh + TILE_B;
        const uint32_t sBh = sAh + 2 * TILE_B;
        const uint32_t sBl = sAh + 3 * TILE_B;

#pragma unroll
        for (int ks = 0; ks < 2; ks++) {
            const uint32_t kbyte = (uint32_t)(ks * 32);

            uint32_t ah[4][4], al[4][4];
#pragma unroll
            for (int i = 0; i < 4; i++) {
                const uint32_t ro = (uint32_t)((wm * 64 + i * 16) * (PADK*2)) + kbyte;
                ldmatrix_x4(ah[i], sAh + ro + a_off);
                ldmatrix_x4(al[i], sAl + ro + a_off);
            }
            uint32_t bh[2][4], bl[2][4];
#pragma unroll
            for (int p = 0; p < 2; p++) {
                const uint32_t ro = (uint32_t)((wn * 32 + p * 16) * (PADK*2)) + kbyte;
                ldmatrix_x4(bh[p], sBh + ro + b_off);
                ldmatrix_x4(bl[p], sBl + ro + b_off);
            }
#pragma unroll
            for (int i = 0; i < 4; i++)
#pragma unroll
                for (int j = 0; j < 4; j++) {
                    const int p = j >> 1, u = (j & 1) * 2;
                    mma_f16(acc[i][j], ah[i], bh[p][u], bh[p][u+1]);
                    mma_f16(acc[i][j], ah[i], bl[p][u], bl[p][u+1]);
                    mma_f16(acc[i][j], al[i], bh[p][u], bh[p][u+1]);
                }
        }
        __syncthreads();
    }
#undef ISSUE3

    const int rbase = m0 + wm * 64 + (lane >> 2);
    const int cbase = n0 + wn * 32 + (lane & 3) * 2;
#pragma unroll
    for (int i = 0; i < 4; i++)
#pragma unroll
        for (int j = 0; j < 4; j++) {
            float* p0 = C + (size_t)(rbase + i * 16) * NN + cbase + j * 8;
            float* p1 = p0 + 8 * (size_t)NN;
            *(float2*)p0 = make_float2(acc[i][j][0], acc[i][j][1]);
            *(float2*)p1 = make_float2(acc[i][j][2], acc[i][j][3]);
        }
}

// ---------------------------------------------------------------------------
// Output projection, 2-pass split-fp16 HMMA:
//   out = ao_h * (Wo_h + Wo_l)^T      (ao quantization error ~2.7e-4 accepted)
// ---------------------------------------------------------------------------
#define STAGE2_B (3 * TILE_B)
#define WO_SMEM (2 * STAGE2_B)      // 61440

__global__ void __launch_bounds__(256) gemm_wo(
    const __half* __restrict__ Ah,
    const __half* __restrict__ Bh, const __half* __restrict__ Bl,
    float* __restrict__ C)
{
    extern __shared__ char smem[];
    const uint32_t sbase = smem_u32(smem);
    const int K = QCOLS, NN = HH;

    const int tid  = threadIdx.x;
    const int wid  = tid >> 5, lane = tid & 31;
    const int wm   = wid >> 2;
    const int wn   = wid & 3;
    const int m0   = blockIdx.y * 128, n0 = blockIdx.x * 128;

    const __half* gb[3] = {
        Ah + (size_t)m0 * K, Bh + (size_t)n0 * K, Bl + (size_t)n0 * K };

    const int NC = K >> 5;

#define ISSUE2(c, s) do {                                                     \
    _Pragma("unroll")                                                         \
    for (int i = 0; i < 6; i++) {                                             \
        int e    = tid + i * 256;                                             \
        int t    = e >> 9;                                                    \
        int rem  = e & 511;                                                   \
        int row  = rem >> 2;                                                  \
        int c16  = rem & 3;                                                   \
        uint32_t sa = sbase + (s) * STAGE2_B + t * TILE_B + row * (PADK*2) + c16 * 16; \
        cp_async16(sa, gb[t] + (size_t)row * K + (c) * 32 + c16 * 8);         \
    }                                                                         \
    asm volatile("cp.async.commit_group;" ::: "memory");                      \
} while (0)

    float acc[4][4][4];
#pragma unroll
    for (int i = 0; i < 4; i++)
#pragma unroll
        for (int j = 0; j < 4; j++)
#pragma unroll
            for (int r = 0; r < 4; r++) acc[i][j][r] = 0.f;

    const uint32_t a_off = (uint32_t)((lane & 15) * (PADK*2) + (lane >> 4) * 16);
    const uint32_t b_off = (uint32_t)(((lane & 7) + ((lane >> 4) << 3)) * (PADK*2)
                                      + ((lane >> 3) & 1) * 16);

    ISSUE2(0, 0);

    for (int c = 0; c < NC; c++) {
        const int s = c & 1;
        if (c + 1 < NC) {
            ISSUE2(c + 1, (c + 1) & 1);
            asm volatile("cp.async.wait_group 1;" ::: "memory");
        } else {
            asm volatile("cp.async.wait_group 0;" ::: "memory");
        }
        __syncthreads();

        const uint32_t sAh = sbase + s * STAGE2_B;
        const uint32_t sBh = sAh + TILE_B;
        const uint32_t sBl = sAh + 2 * TILE_B;

#pragma unroll
        for (int ks = 0; ks < 2; ks++) {
            const uint32_t kbyte = (uint32_t)(ks * 32);

            uint32_t ah[4][4];
#pragma unroll
            for (int i = 0; i < 4; i++) {
                const uint32_t ro = (uint32_t)((wm * 64 + i * 16) * (PADK*2)) + kbyte;
                ldmatrix_x4(ah[i], sAh + ro + a_off);
            }
            uint32_t bh[2][4], bl[2][4];
#pragma unroll
            for (int p = 0; p < 2; p++) {
                const uint32_t ro = (uint32_t)((wn * 32 + p * 16) * (PADK*2)) + kbyte;
                ldmatrix_x4(bh[p], sBh + ro + b_off);
                ldmatrix_x4(bl[p], sBl + ro + b_off);
            }
#pragma unroll
            for (int i = 0; i < 4; i++)
#pragma unroll
                for (int j = 0; j < 4; j++) {
                    const int p = j >> 1, u = (j & 1) * 2;
                    mma_f16(acc[i][j], ah[i], bh[p][u], bh[p][u+1]);
                    mma_f16(acc[i][j], ah[i], bl[p][u], bl[p][u+1]);
                }
        }
        __syncthreads();
    }
#undef ISSUE2

    const int rbase = m0 + wm * 64 + (lane >> 2);
    const int cbase = n0 + wn * 32 + (lane & 3) * 2;
#pragma unroll
    for (int i = 0; i < 4; i++)
#pragma unroll
        for (int j = 0; j < 4; j++) {
            float* p0 = C + (size_t)(rbase + i * 16) * NN + cbase + j * 8;
            float* p1 = p0 + 8 * (size_t)NN;
            *(float2*)p0 = make_float2(acc[i][j][0], acc[i][j][1]);
            *(float2*)p1 = make_float2(acc[i][j][2], acc[i][j][3]);
        }
}

// ---------------------------------------------------------------------------
// RMSNorm (+ optional weight) + RoPE; fp32 in, fp16 hi/lo out (v: hi only).
// ---------------------------------------------------------------------------
__global__ void rmsrope_kernel(const float* __restrict__ cosb,
                               const float* __restrict__ sinb,
                               const float* __restrict__ qw,
                               const float* __restrict__ kw)
{
    const int row  = blockIdx.x;
    const int part = blockIdx.y;
    const int d    = threadIdx.x;

    const float* ptr;
    __half *hp, *lp = nullptr;
    const float* w = nullptr;
    bool do_rope = true;
    if (part < 8) {
        size_t off = (size_t)row * QCOLS + part * DD;
        ptr = g_q + off; hp = g_qh + off; lp = g_ql + off; w = qw;
    } else if (part < 12) {
        size_t off = (size_t)row * KVCOLS + (part - 8) * DD;
        ptr = g_k + off; hp = g_kh + off; lp = g_kl + off; w = kw;
    } else {
        size_t off = (size_t)row * KVCOLS + (part - 12) * DD;
        ptr = g_v + off; hp = g_vh + off; do_rope = false;
    }

    float x = ptr[d];
    __shared__ float red[8];
    float ss = x * x;
#pragma unroll
    for (int o = 16; o; o >>= 1) ss += __shfl_xor_sync(0xffffffffu, ss, o);
    if ((d & 31) == 0) red[d >> 5] = ss;
    __syncthreads();
    float tot = red[0]+red[1]+red[2]+red[3]+red[4]+red[5]+red[6]+red[7];

    float y = x * rsqrtf(tot * (1.0f / DD) + 1e-6f);
    if (w) y *= (1.0f + w[d]);

    if (do_rope) {
        __shared__ float yb[DD];
        yb[d] = y;
        __syncthreads();
        int s = row & (SS - 1);
        float c  = cosb[(size_t)s * DD + d];
        float sn = sinb[(size_t)s * DD + d];
        float other = yb[d ^ 128];
        y = (d < 128) ? (y * c - other * sn) : (y * c + other * sn);
    }
    __half h = __float2half(y);
    hp[d] = h;
    if (lp) lp[d] = __float2half(y - __half2float(h));
}

// ---------------------------------------------------------------------------
// HMMA split-fp16 sliding-window flash attention.
// QK^T: 3-pass (Qh/Ql x Kh/Kl). PV: 2-pass (Ph+Pl)*Vh.
// ---------------------------------------------------------------------------
#define QSTR 528                     // 264 fp16 = 528B row stride
#define QTILE (128 * QSTR)           // 67584
#define KTILE (64 * QSTR)            // 33792
#define ATT_SMEM (2*QTILE + 2*KTILE) // 202752 (K uses 2 tiles; V reuses 1)

__global__ void __launch_bounds__(256, 1) attn_hmma()
{
    extern __shared__ char smem[];
    const uint32_t sb   = smem_u32(smem);
    const uint32_t qh_s = sb;
    const uint32_t ql_s = sb + QTILE;
    const uint32_t kv_s = sb + 2 * QTILE;

    const int qblk = gridDim.x - 1 - blockIdx.x;
    const int h    = blockIdx.y;
    const int b    = blockIdx.z;
    const int kvh  = h >> 1;
    const int tid  = threadIdx.x;
    const int wid  = tid >> 5, lane = tid & 31;
    const int wrow = wid * 16;
    const int qs   = qblk * 128;

    // ---- Q resident load (hi & lo) ----
    {
        const __half* qsrc[2] = {
            g_qh + (size_t)(b*SS + qs) * QCOLS + h * DD,
            g_ql + (size_t)(b*SS + qs) * QCOLS + h * DD };
#pragma unroll
        for (int i = 0; i < 32; i++) {
            int e = tid + i * 256;
            int arr = e >> 12;
            int rem = e & 4095;
            int row = rem >> 5, c16 = rem & 31;
            cp_async16((arr ? ql_s : qh_s) + row * QSTR + c16 * 16,
                       qsrc[arr] + (size_t)row * QCOLS + c16 * 8);
        }
        asm volatile("cp.async.commit_group;" ::: "memory");
    }

    float out[32][4];
#pragma unroll
    for (int nt = 0; nt < 32; nt++)
#pragma unroll
        for (int r = 0; r < 4; r++) out[nt][r] = 0.f;
    float mrow[2] = {-1e30f, -1e30f};
    float lrow[2] = {0.f, 0.f};

    const __half* khg = g_kh + (size_t)(b*SS) * KVCOLS + kvh * DD;
    const __half* klg = g_kl + (size_t)(b*SS) * KVCOLS + kvh * DD;
    const __half* vhg = g_vh + (size_t)(b*SS) * KVCOLS + kvh * DD;

    int ksmin = qs - (SWIN - 1);
    if (ksmin < 0) ksmin = 0;
    const int t0 = ksmin >> 6;
    const int t1 = (qs + 127) >> 6;

    const uint32_t a_off = (uint32_t)((wrow + (lane & 15)) * QSTR + (lane >> 4) * 16);
    const uint32_t b_off = (uint32_t)(((lane & 7) + ((lane >> 4) << 3)) * QSTR
                                      + ((lane >> 3) & 1) * 16);
    const uint32_t v_off = (uint32_t)((lane & 15) * QSTR + (lane >> 4) * 16);

    const int lg = lane >> 2;
    const int lc = (lane & 3) * 2;

    for (int kt = t0; kt <= t1; kt++) {
        const int ks = kt << 6;

        // ---- load K tile (hi, lo) ----
#pragma unroll
        for (int i = 0; i < 16; i++) {
            int e = tid + i * 256;
            int arr = e >> 11;
            int rem = e & 2047;
            int row = rem >> 5, c16 = rem & 31;
            cp_async16(kv_s + arr * KTILE + row * QSTR + c16 * 16,
                       (arr ? klg : khg) + (size_t)(ks + row) * KVCOLS + c16 * 8);
        }
        asm volatile("cp.async.commit_group;" ::: "memory");
        asm volatile("cp.async.wait_group 0;" ::: "memory");
        __syncthreads();

        // ---- S = Q K^T (3-pass) ----
        float sacc[8][4];
#pragma unroll
        for (int j = 0; j < 8; j++)
#pragma unroll
            for (int r = 0; r < 4; r++) sacc[j][r] = 0.f;

#pragma unroll
        for (int ks16 = 0; ks16 < 16; ks16++) {
            uint32_t qf_h[4], qf_l[4];
            ldmatrix_x4(qf_h, qh_s + a_off + ks16 * 32);
            ldmatrix_x4(qf_l, ql_s + a_off + ks16 * 32);
#pragma unroll
            for (int jp = 0; jp < 4; jp++) {
                uint32_t kf_h[4], kf_l[4];
                const uint32_t ro = (uint32_t)(jp * 16 * QSTR) + ks16 * 32;
                ldmatrix_x4(kf_h, kv_s + ro + b_off);
                ldmatrix_x4(kf_l, kv_s + KTILE + ro + b_off);
#pragma unroll
                for (int u = 0; u < 2; u++) {
                    const int j = jp * 2 + u;
                    mma_f16(sacc[j], qf_h, kf_h[u*2], kf_h[u*2+1]);
                    mma_f16(sacc[j], qf_h, kf_l[u*2], kf_l[u*2+1]);
                    mma_f16(sacc[j], qf_l, kf_h[u*2], kf_h[u*2+1]);
                }
            }
        }

        // ---- mask + online softmax (warp-local) ----
        uint32_t ph[8][2], pl[8][2];
#pragma unroll
        for (int g = 0; g < 2; g++) {
            const int qi = qs + wrow + lg + g * 8;
            float mloc = -1e30f;
#pragma unroll
            for (int j = 0; j < 8; j++)
#pragma unroll
                for (int e = 0; e < 2; e++) {
                    const int kj = ks + j * 8 + lc + e;
                    float s = sacc[j][g*2+e];
                    if (kj > qi || kj <= qi - SWIN) s = -1e30f;
                    sacc[j][g*2+e] = s;
                    mloc = fmaxf(mloc, s);
                }
            mloc = fmaxf(mloc, __shfl_xor_sync(0xffffffffu, mloc, 1));
            mloc = fmaxf(mloc, __shfl_xor_sync(0xffffffffu, mloc, 2));
            const float mnew = fmaxf(mrow[g], mloc);
            const float corr = __expf(mrow[g] - mnew);
            float ls = 0.f;
#pragma unroll
            for (int j = 0; j < 8; j++)
#pragma unroll
                for (int e = 0; e < 2; e++) {
                    float s = sacc[j][g*2+e];
                    float p = (s <= -1e29f) ? 0.f : __expf(s - mnew);
                    sacc[j][g*2+e] = p;
                    ls += p;
                }
            ls += __shfl_xor_sync(0xffffffffu, ls, 1);
            ls += __shfl_xor_sync(0xffffffffu, ls, 2);
            lrow[g] = lrow[g] * corr + ls;
            mrow[g] = mnew;
#pragma unroll
            for (int nt = 0; nt < 32; nt++) {
                out[nt][g*2+0] *= corr;
                out[nt][g*2+1] *= corr;
            }
        }
        // pack P -> fp16 hi/lo A-fragments
#pragma unroll
        for (int j = 0; j < 8; j++)
#pragma unroll
            for (int g = 0; g < 2; g++) {
                float v0 = sacc[j][g*2+0], v1 = sacc[j][g*2+1];
                __half h0 = __float2half(v0);
                __half h1 = __float2half(v1);
                __half2 hh; hh.x = h0; hh.y = h1;
                ph[j][g] = *(uint32_t*)&hh;
                pl[j][g] = pack_h2(v0 - __half2float(h0), v1 - __half2float(h1));
            }

        __syncthreads();   // all warps done reading K smem

        // ---- load V tile (hi only) ----
#pragma unroll
        for (int i = 0; i < 8; i++) {
            int e = tid + i * 256;
            int row = e >> 5, c16 = e & 31;
            cp_async16(kv_s + row * QSTR + c16 * 16,
                       vhg + (size_t)(ks + row) * KVCOLS + c16 * 8);
        }
        asm volatile("cp.async.commit_group;" ::: "memory");
        asm volatile("cp.async.wait_group 0;" ::: "memory");
        __syncthreads();

        // ---- O += P V (2-pass: (Ph+Pl) * Vh) ----
#pragma unroll
        for (int s = 0; s < 4; s++) {
            uint32_t aph[4] = { ph[2*s][0], ph[2*s][1], ph[2*s+1][0], ph[2*s+1][1] };
            uint32_t apl[4] = { pl[2*s][0], pl[2*s][1], pl[2*s+1][0], pl[2*s+1][1] };
            const uint32_t krow = (uint32_t)(s * 16 * QSTR);
#pragma unroll
            for (int np = 0; np < 16; np++) {
                uint32_t vf_h[4];
                const uint32_t vo = krow + (uint32_t)(np * 32) + v_off;
                ldmatrix_x4_t(vf_h, kv_s + vo);
#pragma unroll
                for (int u = 0; u < 2; u++) {
                    const int nt = np * 2 + u;
                    mma_f16(out[nt], aph, vf_h[u*2], vf_h[u*2+1]);
                    mma_f16(out[nt], apl, vf_h[u*2], vf_h[u*2+1]);
                }
            }
        }
        __syncthreads();
    }

    // ---- epilogue: divide by l, store fp16 hi ----
#pragma unroll
    for (int g = 0; g < 2; g++) {
        const float inv = 1.0f / lrow[g];
        const int row = qs + wrow + lg + g * 8;
        __half* oh = g_ao_h + (size_t)(b*SS + row) * QCOLS + h * DD + lc;
#pragma unroll
        for (int nt = 0; nt < 32; nt++) {
            *(uint32_t*)(oh + nt*8) = pack_h2(out[nt][g*2+0] * inv,
                                              out[nt][g*2+1] * inv);
        }
    }
}

// ---------------------------------------------------------------------------
extern "C" void kernel_launch(void* const* d_in, const int* in_sizes, int n_in,
                              void* d_out, int out_size)
{
    (void)in_sizes; (void)n_in; (void)out_size;
    const float* hidden = (const float*)d_in[0];
    // d_in[1] = attention_mask — analytic, unused
    const float* cosb = (const float*)d_in[2];
    const float* sinb = (const float*)d_in[3];
    const float* Wq = (const float*)d_in[4];
    const float* Wk = (const float*)d_in[5];
    const float* Wv = (const float*)d_in[6];
    const float* Wo = (const float*)d_in[7];
    const float* qw = (const float*)d_in[8];
    const float* kw = (const float*)d_in[9];
    float* out = (float*)d_out;

    float *qp, *kp, *vp;
    cudaGetSymbolAddress((void**)&qp, g_q);
    cudaGetSymbolAddress((void**)&kp, g_k);
    cudaGetSymbolAddress((void**)&vp, g_v);
    __half *hid_h, *hid_l, *wq_h, *wq_l, *wk_h, *wk_l, *wv_h, *wv_l,
           *wo_h, *wo_l, *ao_h;
    cudaGetSymbolAddress((void**)&hid_h, g_hid_h);
    cudaGetSymbolAddress((void**)&hid_l, g_hid_l);
    cudaGetSymbolAddress((void**)&wq_h,  g_wq_h);
    cudaGetSymbolAddress((void**)&wq_l,  g_wq_l);
    cudaGetSymbolAddress((void**)&wk_h,  g_wk_h);
    cudaGetSymbolAddress((void**)&wk_l,  g_wk_l);
    cudaGetSymbolAddress((void**)&wv_h,  g_wv_h);
    cudaGetSymbolAddress((void**)&wv_l,  g_wv_l);
    cudaGetSymbolAddress((void**)&wo_h,  g_wo_h);
    cudaGetSymbolAddress((void**)&wo_l,  g_wo_l);
    cudaGetSymbolAddress((void**)&ao_h,  g_ao_h);

    cudaFuncSetAttribute(gemm_qkv, cudaFuncAttributeMaxDynamicSharedMemorySize, QKV_SMEM);
    cudaFuncSetAttribute(gemm_wo,  cudaFuncAttributeMaxDynamicSharedMemorySize, WO_SMEM);
    cudaFuncSetAttribute(attn_hmma, cudaFuncAttributeMaxDynamicSharedMemorySize, ATT_SMEM);

    // 0) split fp32 -> fp16 hi/lo
    {
        int n4;
        n4 = (int)((size_t)MROWS * HH / 4);
        split_kernel<<<(n4 + 255) / 256, 256>>>(hidden, hid_h, hid_l, n4);
        n4 = (int)((size_t)QCOLS * HH / 4);
        split_kernel<<<(n4 + 255) / 256, 256>>>(Wq, wq_h, wq_l, n4);
        n4 = (int)((size_t)KVCOLS * HH / 4);
        split_kernel<<<(n4 + 255) / 256, 256>>>(Wk, wk_h, wk_l, n4);
        split_kernel<<<(n4 + 255) / 256, 256>>>(Wv, wv_h, wv_l, n4);
        n4 = (int)((size_t)HH * QCOLS / 4);
        split_kernel<<<(n4 + 255) / 256, 256>>>(Wo, wo_h, wo_l, n4);
    }

    // 1) fused QKV projection (3-pass fp16 HMMA)
    gemm_qkv<<<dim3(32, 32), 256, QKV_SMEM>>>(
        hid_h, hid_l, wq_h, wq_l, wk_h, wk_l, wv_h, wv_l, qp, kp, vp);

    // 2) RMSNorm + RoPE -> fp16 hi/lo (v: hi only)
    rmsrope_kernel<<<dim3(MROWS, NHQ + 2*NKV), 256>>>(cosb, sinb, qw, kw);

    // 3) HMMA sliding-window flash attention -> fp16 ao
    attn_hmma<<<dim3(SS/128, NHQ, BB), 256, ATT_SMEM>>>();

    // 4) output projection (2-pass fp16 HMMA) -> fp32 d_out
    gemm_wo<<<dim3(HH/128, MROWS/128), 256, WO_SMEM>>>(ao_h, wo_h, wo_l, out);
}